// round 11
// baseline (speedup 1.0000x reference)
#include <cuda_runtime.h>
#include <cuda_bf16.h>
#include <math.h>

// Problem constants
#define DD      256
#define KCODES  8192
#define BATCH   8
#define HW      1024
#define NTOK    8192

// Output layout (flattened return tuple, in order)
#define OUT_Q     0
#define OUT_LOSS  2097152
#define OUT_PERP  2097153
#define OUT_IDX   2097154
#define OUT_DW    2105346
#define OUT_CS    4202498

// GEMM config: C[8192 tok, 8192 codes] = A[.,768] * B[.,768]^T  (bf16x3 split)
#define KTOT    768
#define MTILE   128
#define NTILE   128
#define KS      64
#define NSTAGES 12                    // 768/64
#define NPIPE   3                     // cp.async pipeline depth
#define NSPLITS (KCODES / NTILE)      // 64
#define ABYTES  16384                 // per-stage A buffer (128 x 128B)
#define BBYTES  16384                 // per-stage B buffer
#define SM_RED  (NPIPE * (ABYTES + BBYTES))    // 98304: sred after tiles
#define SMEM_DYN (SM_RED + 4096)               // 100KB/CTA -> 2 CTAs/SM

typedef unsigned long long ull;
typedef unsigned int uint;

// ---------------- device scratch (no allocation allowed) --------------------
__device__ __nv_bfloat16 g_A[NTOK   * KTOT];  // [tok ][xh(256)|xh(256)|xl(256)]
__device__ __nv_bfloat16 g_B[KCODES * KTOT];  // [code][eh(256)|el(256)|eh(256)]
__device__ float  g_zT[NTOK   * DD];          // fp32 z, token-major (exact copy)
__device__ float  g_ET[KCODES * DD];          // fp32 E, code-major (exact copy)
__device__ float  g_e2[KCODES];
__device__ float  g_sx2[NTOK];
__device__ ull    g_top1[NTOK * NSPLITS];     // [token][split]
__device__ ull    g_top2[NTOK * NSPLITS];
__device__ double g_loss;
__device__ int    g_ticket;

// ---------------- PTX helpers (all plain-sm_100 legal) ----------------------
__device__ __forceinline__ uint smem_u32(const void* p) {
    uint a;
    asm("{ .reg .u64 t; cvta.to.shared.u64 t, %1; cvt.u32.u64 %0, t; }"
        : "=r"(a) : "l"(p));
    return a;
}
#define CP16(dst, src) \
    asm volatile("cp.async.cg.shared.global [%0], [%1], 16;" :: "r"(dst), "l"(src))
#define CP_COMMIT() asm volatile("cp.async.commit_group;")
#define CP_WAIT(n)  asm volatile("cp.async.wait_group %0;" :: "n"(n))

#define LDSM4(r0, r1, r2, r3, a) \
    asm volatile("ldmatrix.sync.aligned.m8n8.x4.shared.b16 {%0,%1,%2,%3}, [%4];" \
        : "=r"(r0), "=r"(r1), "=r"(r2), "=r"(r3) : "r"(a))

#define MMA16816(c, a, b) \
    asm volatile("mma.sync.aligned.m16n8k16.row.col.f32.bf16.bf16.f32 " \
        "{%0,%1,%2,%3}, {%4,%5,%6,%7}, {%8,%9}, {%0,%1,%2,%3};" \
        : "+f"((c)[0]), "+f"((c)[1]), "+f"((c)[2]), "+f"((c)[3]) \
        : "r"((a)[0]), "r"((a)[1]), "r"((a)[2]), "r"((a)[3]), \
          "r"((b)[0]), "r"((b)[1]))

__device__ __forceinline__ ull umax(ull a, ull b) { return a > b ? a : b; }
__device__ __forceinline__ ull umin(ull a, ull b) { return a < b ? a : b; }

// ---------------------------------------------------------------------------
// K_prep (fused init + norms + transpose/split + fp32 transposed copies):
//   Blocks 0..255:   z -> g_A (32 tokens each) + g_sx2 + g_zT
//   Blocks 256..511: E -> g_B (32 codes each)  + g_e2  + g_ET
// ---------------------------------------------------------------------------
__global__ void k_prep(const float* __restrict__ z, const float* __restrict__ E,
                       float* __restrict__ out) {
    __shared__ float st[32 * 264];
    const int tid = threadIdx.x;
    const bool isB = blockIdx.x >= 256;
    const int n0 = (isB ? (blockIdx.x - 256) : blockIdx.x) * 32;

    // zero dw + cluster_size (2105344 floats = 1052672 float2, 8B-aligned)
    {
        const float2 z2 = make_float2(0.0f, 0.0f);
        float2* dst2 = (float2*)(out + OUT_DW);
        for (int i = blockIdx.x * 256 + tid; i < 1052672; i += 512 * 256)
            dst2[i] = z2;
        if (blockIdx.x == 0 && tid == 0) { g_loss = 0.0; g_ticket = 0; }
    }

    // load 32 rows x 256 dims into smem (transposed)
    for (int i = tid; i < 32 * 256; i += 256) {
        int k = i >> 5, nl = i & 31;
        float v;
        if (isB) v = E[k * KCODES + n0 + nl];
        else {
            int b = n0 >> 10, hw0 = n0 & 1023;
            v = z[(b * DD + k) * HW + hw0 + nl];
        }
        st[nl * 264 + k] = v;
    }
    __syncthreads();

    // norms: one thread per row, sequential fp32 over d (bit-identical path)
    if (tid < 32) {
        float s = 0.0f;
        #pragma unroll 8
        for (int d = 0; d < DD; d++) { float v = st[tid * 264 + d]; s += v * v; }
        if (isB) g_e2[n0 + tid] = s;
        else     g_sx2[n0 + tid] = s;
    }

    const int nl = tid >> 3;
    const int jb = (tid & 7) * 32;

    // fp32 transposed copy (exact values, row-contiguous)
    {
        float* tdst = (isB ? g_ET : g_zT) + (ull)(n0 + nl) * DD + jb;
        #pragma unroll
        for (int t = 0; t < 8; t++) {
            float4 v = make_float4(st[nl * 264 + jb + 4 * t],
                                   st[nl * 264 + jb + 4 * t + 1],
                                   st[nl * 264 + jb + 4 * t + 2],
                                   st[nl * 264 + jb + 4 * t + 3]);
            *(float4*)(tdst + 4 * t) = v;
        }
    }

    // bf16 hi/lo split, packed stores:  A row [xh|xh|xl],  B row [eh|el|eh]
    __nv_bfloat16* dst = isB ? g_B : g_A;
    __nv_bfloat16* rowp = dst + (ull)(n0 + nl) * KTOT;

    uint hwv[16], lwv[16];
    #pragma unroll
    for (int t = 0; t < 16; t++) {
        float v0 = st[nl * 264 + jb + 2 * t];
        float v1 = st[nl * 264 + jb + 2 * t + 1];
        __nv_bfloat16 h0 = __float2bfloat16(v0);
        __nv_bfloat16 h1 = __float2bfloat16(v1);
        __nv_bfloat16 l0 = __float2bfloat16(v0 - __bfloat162float(h0));
        __nv_bfloat16 l1 = __float2bfloat16(v1 - __bfloat162float(h1));
        hwv[t] = (uint)__bfloat16_as_ushort(h0) | ((uint)__bfloat16_as_ushort(h1) << 16);
        lwv[t] = (uint)__bfloat16_as_ushort(l0) | ((uint)__bfloat16_as_ushort(l1) << 16);
    }
    uint4* p0 = (uint4*)(rowp + jb);            // hi
    uint4* p1 = (uint4*)(rowp + 256 + jb);      // B: lo,  A: hi
    uint4* p2 = (uint4*)(rowp + 512 + jb);      // B: hi,  A: lo
    #pragma unroll
    for (int t = 0; t < 4; t++) {
        uint4 hv = make_uint4(hwv[4*t], hwv[4*t+1], hwv[4*t+2], hwv[4*t+3]);
        uint4 lv = make_uint4(lwv[4*t], lwv[4*t+1], lwv[4*t+2], lwv[4*t+3]);
        p0[t] = hv;
        p1[t] = isB ? lv : hv;
        p2[t] = isB ? hv : lv;
    }
}

// ---------------------------------------------------------------------------
// K1: HMMA bf16 distance GEMM fused with per-token top-2 (R9 config, best
// measured). CTA tile 128x128, 4 warps (2m x 2n), warp tile 64x64, NPIPE=3,
// 100KB smem -> 2 CTAs/SM. Grid (64 m-tiles, 64 n-blocks).
// ---------------------------------------------------------------------------
__global__ void __launch_bounds__(128, 2)
k_mma() {
    extern __shared__ char smem[];
    const uint sb  = smem_u32(smem);
    const uint sA  = sb;                       // 3 x 16KB
    const uint sB  = sb + NPIPE * ABYTES;      // 3 x 16KB
    ull* sred = (ull*)(smem + SM_RED);         // 4KB, separate from tiles

    const int tid  = threadIdx.x;
    const int lane = tid & 31;
    const int wid  = tid >> 5;      // 0..3
    const int wm   = wid & 1;       // m warp (2): 64 rows each
    const int wn   = wid >> 1;      // n warp (2): 64 cols each

    const int m0   = blockIdx.x * MTILE;
    const int nblk = blockIdx.y;
    const int n0   = nblk * NTILE;

    const __nv_bfloat16* gA = g_A + (ull)m0 * KTOT;
    const __nv_bfloat16* gB = g_B + (ull)n0 * KTOT;

    float c[4][8][4];
    #pragma unroll
    for (int i = 0; i < 4; i++)
        #pragma unroll
        for (int j = 0; j < 8; j++)
            #pragma unroll
            for (int r = 0; r < 4; r++) c[i][j][r] = 0.0f;

    // --- hoisted issue-side address components (tid-constant) ---
    const int ld_row = tid >> 3;           // 0..15
    const int ld_ch  = tid & 7;
    const uint ld_sw = (uint)((ld_ch ^ (ld_row & 7)) << 4);
    const uint dst_base = (uint)ld_row * 128u + ld_sw;
    const __nv_bfloat16* srcA0 = gA + (ull)ld_row * KTOT + ld_ch * 8;
    const __nv_bfloat16* srcB0 = gB + (ull)ld_row * KTOT + ld_ch * 8;

    // --- hoisted ldmatrix address components ---
    const int rowA = wm * 64 + (lane & 7) + ((lane >> 3) & 1) * 8;  // + i*16
    const int chA  = (lane >> 4);
    const int rowB = wn * 64 + (lane & 7) + ((lane >> 4) << 3);     // + nb*16
    const int chB  = (lane >> 3) & 1;
    uint colA[4], colB[4];
    #pragma unroll
    for (int ks = 0; ks < 4; ks++) {
        colA[ks] = (uint)(((ks * 2 + chA) ^ (rowA & 7)) << 4);
        colB[ks] = (uint)(((ks * 2 + chB) ^ (rowB & 7)) << 4);
    }
    uint rbaseA[4], rbaseB[4];
    #pragma unroll
    for (int i = 0; i < 4; i++) rbaseA[i] = (uint)(rowA + i * 16) * 128u;
    #pragma unroll
    for (int i = 0; i < 4; i++) rbaseB[i] = (uint)(rowB + i * 16) * 128u;

    // stage issuer: 8 A-chunks + 8 B-chunks of 16B per thread (128 threads)
    auto issue = [&](int s, int buf) {
        const int kb = s * KS;
        const uint bufA = sA + (uint)buf * ABYTES;
        const uint bufB = sB + (uint)buf * BBYTES;
        const __nv_bfloat16* sa  = srcA0 + kb;
        const __nv_bfloat16* sbp = srcB0 + kb;
        #pragma unroll
        for (int i = 0; i < 8; i++)
            CP16(bufA + dst_base + (uint)i * 2048u, sa + (ull)i * 16 * KTOT);
        #pragma unroll
        for (int i = 0; i < 8; i++)
            CP16(bufB + dst_base + (uint)i * 2048u, sbp + (ull)i * 16 * KTOT);
        CP_COMMIT();
    };

    issue(0, 0); issue(1, 1);

    int buf = 0;
    for (int s = 0; s < NSTAGES; s++) {
        if (s < NSTAGES - 1) { CP_WAIT(1); } else { CP_WAIT(0); }
        __syncthreads();

        const uint bufA = sA + (uint)buf * ABYTES;
        const uint bufB = sB + (uint)buf * BBYTES;

        #pragma unroll
        for (int ks = 0; ks < 4; ks++) {
            uint a[4][4];
            #pragma unroll
            for (int i = 0; i < 4; i++)
                LDSM4(a[i][0], a[i][1], a[i][2], a[i][3],
                      bufA + rbaseA[i] + colA[ks]);
            uint b[8][2];
            #pragma unroll
            for (int nb = 0; nb < 4; nb++) {
                uint r0, r1, r2, r3;
                LDSM4(r0, r1, r2, r3, bufB + rbaseB[nb] + colB[ks]);
                b[nb * 2][0] = r0;     b[nb * 2][1] = r1;
                b[nb * 2 + 1][0] = r2; b[nb * 2 + 1][1] = r3;
            }
            #pragma unroll
            for (int i = 0; i < 4; i++)
                #pragma unroll
                for (int j = 0; j < 8; j++)
                    MMA16816(c[i][j], a[i], b[j]);
        }
        if (s + 2 < NSTAGES) {
            int nbuf = buf + 2; if (nbuf >= NPIPE) nbuf -= NPIPE;
            issue(s + 2, nbuf);
        }
        if (++buf == NPIPE) buf = 0;
    }

    // ---------------- epilogue: dist + top-2, no atomics --------------------
    float e2v[8][2];
    #pragma unroll
    for (int j = 0; j < 8; j++)
        #pragma unroll
        for (int q = 0; q < 2; q++)
            e2v[j][q] = g_e2[n0 + wn * 64 + j * 8 + (lane & 3) * 2 + q];

    #pragma unroll
    for (int i = 0; i < 4; i++) {
        #pragma unroll
        for (int h = 0; h < 2; h++) {
            const int m_local = wm * 64 + i * 16 + (lane >> 2) + h * 8;
            const float sx2 = g_sx2[m0 + m_local];
            ull b1 = 0ull, b2 = 0ull;
            #pragma unroll
            for (int j = 0; j < 8; j++) {
                #pragma unroll
                for (int q = 0; q < 2; q++) {
                    float dot  = c[i][j][h * 2 + q];
                    float dist = (sx2 - 2.0f * dot) + e2v[j][q];
                    const int n = n0 + wn * 64 + j * 8 + (lane & 3) * 2 + q;
                    uint u = __float_as_uint(dist);
                    uint m = (u & 0x80000000u) ? ~u : (u | 0x80000000u);
                    ull key = ((ull)(~m) << 32) | (uint)(KCODES - 1 - n);
                    if (key > b1)      { b2 = b1; b1 = key; }
                    else if (key > b2) { b2 = key; }
                }
            }
            #pragma unroll
            for (int sh = 1; sh <= 2; sh <<= 1) {
                ull o1 = __shfl_xor_sync(0xffffffffu, b1, sh);
                ull o2 = __shfl_xor_sync(0xffffffffu, b2, sh);
                ull n1 = umax(b1, o1);
                ull n2 = umax(umin(b1, o1), umax(b2, o2));
                b1 = n1; b2 = n2;
            }
            if ((lane & 3) == 0) {
                sred[(m_local * 2 + wn) * 2 + 0] = b1;
                sred[(m_local * 2 + wn) * 2 + 1] = b2;
            }
        }
    }
    __syncthreads();
    {
        const int row = tid;   // 128 rows, 128 threads
        ull p1a = sred[(row * 2 + 0) * 2 + 0], p2a = sred[(row * 2 + 0) * 2 + 1];
        ull p1b = sred[(row * 2 + 1) * 2 + 0], p2b = sred[(row * 2 + 1) * 2 + 1];
        ull b1 = umax(p1a, p1b);
        ull b2 = umax(umin(p1a, p1b), umax(p2a, p2b));
        g_top1[(ull)(m0 + row) * NSPLITS + nblk] = b1;   // [token][split]
        g_top2[(ull)(m0 + row) * NSPLITS + nblk] = b2;
    }
}

// ---------------------------------------------------------------------------
// K_post: fused assign + scatter + final. 256 blocks x 256 threads; block =
// 32 consecutive tokens (same batch b, hw = hw0..hw0+31).
//  Phase 1: warp-per-token split merge + near-tie exact fp32 fixup (reads
//           z_T/E_T coalesced; identical fmaf order -> identical decisions).
//  Phase 2: gather E_T[idx] rows coalesced into padded smem; loss + dw
//           atomics; transposed coalesced NCHW write of quantized.
//  Phase 3: last block (ticket) computes loss + perplexity.
// ---------------------------------------------------------------------------
__global__ void __launch_bounds__(256)
k_post(float* __restrict__ out) {
    __shared__ int   s_idx[32];
    __shared__ float q_s[32][257];
    __shared__ float red[256];
    __shared__ int   s_last;

    const int tid  = threadIdx.x;
    const int lane = tid & 31;
    const int w    = tid >> 5;       // 8 warps
    const int n0   = blockIdx.x * 32;
    const int b    = n0 >> 10;
    const int hw0  = n0 & 1023;

    // ---- phase 1: indices for 32 tokens (warp w -> tokens w, w+8, w+16, w+24)
    for (int r = 0; r < 4; r++) {
        const int tt = w + r * 8;
        const int n  = n0 + tt;
        const ull* t1p = g_top1 + (ull)n * NSPLITS;
        const ull* t2p = g_top2 + (ull)n * NSPLITS;
        ull b1 = 0ull, b2 = 0ull;
        #pragma unroll
        for (int rr = 0; rr < 2; rr++) {
            int s = lane + rr * 32;
            ull t1 = t1p[s], t2 = t2p[s];
            if (t1 > b1)      { b2 = b1; b1 = t1; }
            else if (t1 > b2) { b2 = t1; }
            if (t2 > b2)      { b2 = t2; }
        }
        #pragma unroll
        for (int sh = 16; sh >= 1; sh >>= 1) {
            ull o1 = __shfl_xor_sync(0xffffffffu, b1, sh);
            ull o2 = __shfl_xor_sync(0xffffffffu, b2, sh);
            ull n1 = umax(b1, o1);
            ull n2 = umax(umin(b1, o1), umax(b2, o2));
            b1 = n1; b2 = n2;
        }

        int i1 = (KCODES - 1) - (int)(uint)(b1 & 0xffffffffu);
        int i2 = (KCODES - 1) - (int)(uint)(b2 & 0xffffffffu);
        uint m1 = ~(uint)(b1 >> 32), m2 = ~(uint)(b2 >> 32);
        float d1 = __uint_as_float((m1 & 0x80000000u) ? (m1 & 0x7fffffffu) : ~m1);
        float d2 = __uint_as_float((m2 & 0x80000000u) ? (m2 & 0x7fffffffu) : ~m2);

        int idx = i1;
        if (d2 - d1 < 2e-4f) {
            // exact fp32 re-score (same fmaf order as all passing rounds)
            const float* zp  = g_zT + (ull)n * DD;
            const float* ep1 = g_ET + (ull)i1 * DD;
            const float* ep2 = g_ET + (ull)i2 * DD;
            float dot1 = 0.0f, dot2 = 0.0f;
            #pragma unroll
            for (int t = 0; t < 8; t++) {
                int d = t * 32 + lane;
                float zv = zp[d];
                dot1 = fmaf(zv, ep1[d], dot1);
                dot2 = fmaf(zv, ep2[d], dot2);
            }
            #pragma unroll
            for (int sh = 16; sh >= 1; sh >>= 1) {
                dot1 += __shfl_xor_sync(0xffffffffu, dot1, sh);
                dot2 += __shfl_xor_sync(0xffffffffu, dot2, sh);
            }
            float sx2 = g_sx2[n];
            float e1  = (sx2 - 2.0f * dot1) + g_e2[i1];
            float e2x = (sx2 - 2.0f * dot2) + g_e2[i2];
            if (e2x < e1 || (e2x == e1 && i2 < i1)) idx = i2;
        }
        if (lane == 0) {
            s_idx[tt] = idx;
            out[OUT_IDX + n] = (float)idx;
            atomicAdd(&out[OUT_CS + idx], 1.0f);
        }
    }
    __syncthreads();

    // ---- phase 2a: gather E_T rows (coalesced), loss, dw atomics
    float lacc = 0.0f;
    for (int r = 0; r < 4; r++) {
        const int tt  = w + r * 8;
        const int n   = n0 + tt;
        const int idx = s_idx[tt];
        const float* ep = g_ET + (ull)idx * DD;
        const float* zp = g_zT + (ull)n * DD;
        #pragma unroll
        for (int c2 = 0; c2 < 8; c2++) {
            int d = c2 * 32 + lane;
            float q  = ep[d];
            float zv = zp[d];
            q_s[tt][d] = q;
            float df = q - zv;
            lacc += df * df;
            atomicAdd(&out[OUT_DW + d * KCODES + idx], zv);
        }
    }
    __syncthreads();

    // ---- phase 2b: quantized NCHW, fully coalesced (token tt = lane)
    const int ty = tid >> 5;
    #pragma unroll
    for (int dc = 0; dc < 32; dc++) {
        int d = dc * 8 + ty;
        out[OUT_Q + (b * DD + d) * HW + hw0 + lane] = q_s[lane][d];
    }

    // ---- loss block-reduce + ticket
    red[tid] = lacc;
    __syncthreads();
    #pragma unroll
    for (int s = 128; s > 0; s >>= 1) {
        if (tid < s) red[tid] += red[tid + s];
        __syncthreads();
    }
    if (tid == 0) atomicAdd(&g_loss, (double)red[0]);
    __threadfence();
    if (tid == 0) s_last = atomicAdd(&g_ticket, 1);
    __syncthreads();

    // ---- phase 3: last block computes loss + perplexity
    if (s_last == 255) {
        float s = 0.0f;
        for (int k = tid; k < KCODES; k += 256) {
            float p = __ldcg(&out[OUT_CS + k]) * (1.0f / 8192.0f);
            s += p * logf(p + 1e-10f);
        }
        red[tid] = s;
        __syncthreads();
        #pragma unroll
        for (int st = 128; st > 0; st >>= 1) {
            if (tid < st) red[tid] += red[tid + st];
            __syncthreads();
        }
        if (tid == 0) {
            double total = atomicAdd(&g_loss, 0.0);   // atomic read
            out[OUT_PERP] = expf(-red[0]);
            out[OUT_LOSS] = (float)(0.25 * total / 2097152.0);
            g_ticket = 0;
        }
    }
}

// ---------------------------------------------------------------------------
extern "C" void kernel_launch(void* const* d_in, const int* in_sizes, int n_in,
                              void* d_out, int out_size) {
    const float* z = (const float*)d_in[0];         // [8,256,32,32]
    const float* E = (const float*)d_in[1];         // [256,8192]
    float* out = (float*)d_out;

    cudaFuncSetAttribute(k_mma, cudaFuncAttributeMaxDynamicSharedMemorySize,
                         SMEM_DYN);

    k_prep <<< 512, 256 >>>(z, E, out);
    k_mma  <<< dim3(NTOK / MTILE, NSPLITS), 128, SMEM_DYN >>>();
    k_post <<< NTOK / 32, 256 >>>(out);
}

// round 12
// speedup vs baseline: 1.0619x; 1.0619x over previous
#include <cuda_runtime.h>
#include <cuda_bf16.h>
#include <math.h>

// Problem constants
#define DD      256
#define KCODES  8192
#define BATCH   8
#define HW      1024
#define NTOK    8192

// Output layout (flattened return tuple, in order)
#define OUT_Q     0
#define OUT_LOSS  2097152
#define OUT_PERP  2097153
#define OUT_IDX   2097154
#define OUT_DW    2105346
#define OUT_CS    4202498

// GEMM config: C[8192 tok, 8192 codes] = A[.,768] * B[.,768]^T  (bf16x3 split)
#define KTOT    768
#define MTILE   128
#define NTILE   128
#define KS      64
#define NSTAGES 12                    // 768/64
#define NPIPE   3                     // cp.async pipeline depth
#define NSPLITS (KCODES / NTILE)      // 64
#define ABYTES  16384                 // per-stage A buffer (128 x 128B)
#define BBYTES  16384                 // per-stage B buffer
#define SM_RED  (NPIPE * (ABYTES + BBYTES))    // 98304: sred after tiles
#define SMEM_DYN (SM_RED + 4096)               // 100KB/CTA -> 2 CTAs/SM

typedef unsigned long long ull;
typedef unsigned int uint;

// ---------------- device scratch (no allocation allowed) --------------------
__device__ __nv_bfloat16 g_A[NTOK   * KTOT];  // [tok ][xh(256)|xh(256)|xl(256)]
__device__ __nv_bfloat16 g_B[KCODES * KTOT];  // [code][eh(256)|el(256)|eh(256)]
__device__ float  g_e2[KCODES];
__device__ float  g_sx2[NTOK];
__device__ ull    g_top1[NTOK * NSPLITS];     // [token][split]  (coalesced merge)
__device__ ull    g_top2[NTOK * NSPLITS];
__device__ int    g_idx[NTOK];
__device__ double g_loss;
__device__ int    g_ticket;

// ---------------- PTX helpers (all plain-sm_100 legal) ----------------------
__device__ __forceinline__ uint smem_u32(const void* p) {
    uint a;
    asm("{ .reg .u64 t; cvta.to.shared.u64 t, %1; cvt.u32.u64 %0, t; }"
        : "=r"(a) : "l"(p));
    return a;
}
#define CP16(dst, src) \
    asm volatile("cp.async.cg.shared.global [%0], [%1], 16;" :: "r"(dst), "l"(src))
#define CP_COMMIT() asm volatile("cp.async.commit_group;")
#define CP_WAIT(n)  asm volatile("cp.async.wait_group %0;" :: "n"(n))

#define LDSM4(r0, r1, r2, r3, a) \
    asm volatile("ldmatrix.sync.aligned.m8n8.x4.shared.b16 {%0,%1,%2,%3}, [%4];" \
        : "=r"(r0), "=r"(r1), "=r"(r2), "=r"(r3) : "r"(a))

#define MMA16816(c, a, b) \
    asm volatile("mma.sync.aligned.m16n8k16.row.col.f32.bf16.bf16.f32 " \
        "{%0,%1,%2,%3}, {%4,%5,%6,%7}, {%8,%9}, {%0,%1,%2,%3};" \
        : "+f"((c)[0]), "+f"((c)[1]), "+f"((c)[2]), "+f"((c)[3]) \
        : "r"((a)[0]), "r"((a)[1]), "r"((a)[2]), "r"((a)[3]), \
          "r"((b)[0]), "r"((b)[1]))

__device__ __forceinline__ ull umax(ull a, ull b) { return a > b ? a : b; }
__device__ __forceinline__ ull umin(ull a, ull b) { return a < b ? a : b; }

// ---------------------------------------------------------------------------
// K_prep (fused init + norms + transpose/split, vectorized bf16 stores):
//   Blocks 0..255:   z -> g_A (32 tokens each) + g_sx2
//   Blocks 256..511: E -> g_B (32 codes each)  + g_e2
// ---------------------------------------------------------------------------
__global__ void k_prep(const float* __restrict__ z, const float* __restrict__ E,
                       float* __restrict__ out) {
    __shared__ float st[32 * 264];
    const int tid = threadIdx.x;
    const bool isB = blockIdx.x >= 256;
    const int n0 = (isB ? (blockIdx.x - 256) : blockIdx.x) * 32;

    // zero dw + cluster_size (2105344 floats = 1052672 float2, 8B-aligned)
    {
        const float2 z2 = make_float2(0.0f, 0.0f);
        float2* dst2 = (float2*)(out + OUT_DW);
        for (int i = blockIdx.x * 256 + tid; i < 1052672; i += 512 * 256)
            dst2[i] = z2;
        if (blockIdx.x == 0 && tid == 0) { g_loss = 0.0; g_ticket = 0; }
    }

    // load 32 rows x 256 dims into smem (transposed)
    for (int i = tid; i < 32 * 256; i += 256) {
        int k = i >> 5, nl = i & 31;
        float v;
        if (isB) v = E[k * KCODES + n0 + nl];
        else {
            int b = n0 >> 10, hw0 = n0 & 1023;
            v = z[(b * DD + k) * HW + hw0 + nl];
        }
        st[nl * 264 + k] = v;
    }
    __syncthreads();

    // norms: one thread per row, sequential fp32 over d (bit-identical path)
    if (tid < 32) {
        float s = 0.0f;
        #pragma unroll 8
        for (int d = 0; d < DD; d++) { float v = st[tid * 264 + d]; s += v * v; }
        if (isB) g_e2[n0 + tid] = s;
        else     g_sx2[n0 + tid] = s;
    }

    // bf16 hi/lo split, packed stores:  A row [xh|xh|xl],  B row [eh|el|eh]
    __nv_bfloat16* dst = isB ? g_B : g_A;
    const int nl = tid >> 3;
    const int jb = (tid & 7) * 32;
    __nv_bfloat16* rowp = dst + (ull)(n0 + nl) * KTOT;

    uint hwv[16], lwv[16];
    #pragma unroll
    for (int t = 0; t < 16; t++) {
        float v0 = st[nl * 264 + jb + 2 * t];
        float v1 = st[nl * 264 + jb + 2 * t + 1];
        __nv_bfloat16 h0 = __float2bfloat16(v0);
        __nv_bfloat16 h1 = __float2bfloat16(v1);
        __nv_bfloat16 l0 = __float2bfloat16(v0 - __bfloat162float(h0));
        __nv_bfloat16 l1 = __float2bfloat16(v1 - __bfloat162float(h1));
        hwv[t] = (uint)__bfloat16_as_ushort(h0) | ((uint)__bfloat16_as_ushort(h1) << 16);
        lwv[t] = (uint)__bfloat16_as_ushort(l0) | ((uint)__bfloat16_as_ushort(l1) << 16);
    }
    uint4* p0 = (uint4*)(rowp + jb);            // hi
    uint4* p1 = (uint4*)(rowp + 256 + jb);      // B: lo,  A: hi
    uint4* p2 = (uint4*)(rowp + 512 + jb);      // B: hi,  A: lo
    #pragma unroll
    for (int t = 0; t < 4; t++) {
        uint4 hv = make_uint4(hwv[4*t], hwv[4*t+1], hwv[4*t+2], hwv[4*t+3]);
        uint4 lv = make_uint4(lwv[4*t], lwv[4*t+1], lwv[4*t+2], lwv[4*t+3]);
        p0[t] = hv;
        p1[t] = isB ? lv : hv;
        p2[t] = isB ? hv : lv;
    }
}

// ---------------------------------------------------------------------------
// K1: HMMA bf16 distance GEMM fused with per-token top-2 (R9 config, best
// measured). CTA tile 128x128, 4 warps (2m x 2n), warp tile 64x64, NPIPE=3,
// 100KB smem -> 2 CTAs/SM. Grid (64 m-tiles, 64 n-blocks).
// ---------------------------------------------------------------------------
__global__ void __launch_bounds__(128, 2)
k_mma() {
    extern __shared__ char smem[];
    const uint sb  = smem_u32(smem);
    const uint sA  = sb;                       // 3 x 16KB
    const uint sB  = sb + NPIPE * ABYTES;      // 3 x 16KB
    ull* sred = (ull*)(smem + SM_RED);         // 4KB, separate from tiles

    const int tid  = threadIdx.x;
    const int lane = tid & 31;
    const int wid  = tid >> 5;      // 0..3
    const int wm   = wid & 1;       // m warp (2): 64 rows each
    const int wn   = wid >> 1;      // n warp (2): 64 cols each

    const int m0   = blockIdx.x * MTILE;
    const int nblk = blockIdx.y;
    const int n0   = nblk * NTILE;

    const __nv_bfloat16* gA = g_A + (ull)m0 * KTOT;
    const __nv_bfloat16* gB = g_B + (ull)n0 * KTOT;

    float c[4][8][4];
    #pragma unroll
    for (int i = 0; i < 4; i++)
        #pragma unroll
        for (int j = 0; j < 8; j++)
            #pragma unroll
            for (int r = 0; r < 4; r++) c[i][j][r] = 0.0f;

    // --- hoisted issue-side address components (tid-constant) ---
    const int ld_row = tid >> 3;           // 0..15
    const int ld_ch  = tid & 7;
    const uint ld_sw = (uint)((ld_ch ^ (ld_row & 7)) << 4);
    const uint dst_base = (uint)ld_row * 128u + ld_sw;
    const __nv_bfloat16* srcA0 = gA + (ull)ld_row * KTOT + ld_ch * 8;
    const __nv_bfloat16* srcB0 = gB + (ull)ld_row * KTOT + ld_ch * 8;

    // --- hoisted ldmatrix address components ---
    const int rowA = wm * 64 + (lane & 7) + ((lane >> 3) & 1) * 8;  // + i*16
    const int chA  = (lane >> 4);
    const int rowB = wn * 64 + (lane & 7) + ((lane >> 4) << 3);     // + nb*16
    const int chB  = (lane >> 3) & 1;
    uint colA[4], colB[4];
    #pragma unroll
    for (int ks = 0; ks < 4; ks++) {
        colA[ks] = (uint)(((ks * 2 + chA) ^ (rowA & 7)) << 4);
        colB[ks] = (uint)(((ks * 2 + chB) ^ (rowB & 7)) << 4);
    }
    uint rbaseA[4], rbaseB[4];
    #pragma unroll
    for (int i = 0; i < 4; i++) rbaseA[i] = (uint)(rowA + i * 16) * 128u;
    #pragma unroll
    for (int i = 0; i < 4; i++) rbaseB[i] = (uint)(rowB + i * 16) * 128u;

    // stage issuer: 8 A-chunks + 8 B-chunks of 16B per thread (128 threads)
    auto issue = [&](int s, int buf) {
        const int kb = s * KS;
        const uint bufA = sA + (uint)buf * ABYTES;
        const uint bufB = sB + (uint)buf * BBYTES;
        const __nv_bfloat16* sa  = srcA0 + kb;
        const __nv_bfloat16* sbp = srcB0 + kb;
        #pragma unroll
        for (int i = 0; i < 8; i++)
            CP16(bufA + dst_base + (uint)i * 2048u, sa + (ull)i * 16 * KTOT);
        #pragma unroll
        for (int i = 0; i < 8; i++)
            CP16(bufB + dst_base + (uint)i * 2048u, sbp + (ull)i * 16 * KTOT);
        CP_COMMIT();
    };

    issue(0, 0); issue(1, 1);

    int buf = 0;
    for (int s = 0; s < NSTAGES; s++) {
        if (s < NSTAGES - 1) { CP_WAIT(1); } else { CP_WAIT(0); }
        __syncthreads();

        const uint bufA = sA + (uint)buf * ABYTES;
        const uint bufB = sB + (uint)buf * BBYTES;

        #pragma unroll
        for (int ks = 0; ks < 4; ks++) {
            uint a[4][4];
            #pragma unroll
            for (int i = 0; i < 4; i++)
                LDSM4(a[i][0], a[i][1], a[i][2], a[i][3],
                      bufA + rbaseA[i] + colA[ks]);
            uint b[8][2];
            #pragma unroll
            for (int nb = 0; nb < 4; nb++) {
                uint r0, r1, r2, r3;
                LDSM4(r0, r1, r2, r3, bufB + rbaseB[nb] + colB[ks]);
                b[nb * 2][0] = r0;     b[nb * 2][1] = r1;
                b[nb * 2 + 1][0] = r2; b[nb * 2 + 1][1] = r3;
            }
            #pragma unroll
            for (int i = 0; i < 4; i++)
                #pragma unroll
                for (int j = 0; j < 8; j++)
                    MMA16816(c[i][j], a[i], b[j]);
        }
        if (s + 2 < NSTAGES) {
            int nbuf = buf + 2; if (nbuf >= NPIPE) nbuf -= NPIPE;
            issue(s + 2, nbuf);
        }
        if (++buf == NPIPE) buf = 0;
    }

    // ---------------- epilogue: dist + top-2, no atomics --------------------
    float e2v[8][2];
    #pragma unroll
    for (int j = 0; j < 8; j++)
        #pragma unroll
        for (int q = 0; q < 2; q++)
            e2v[j][q] = g_e2[n0 + wn * 64 + j * 8 + (lane & 3) * 2 + q];

    #pragma unroll
    for (int i = 0; i < 4; i++) {
        #pragma unroll
        for (int h = 0; h < 2; h++) {
            const int m_local = wm * 64 + i * 16 + (lane >> 2) + h * 8;
            const float sx2 = g_sx2[m0 + m_local];
            ull b1 = 0ull, b2 = 0ull;
            #pragma unroll
            for (int j = 0; j < 8; j++) {
                #pragma unroll
                for (int q = 0; q < 2; q++) {
                    float dot  = c[i][j][h * 2 + q];
                    float dist = (sx2 - 2.0f * dot) + e2v[j][q];
                    const int n = n0 + wn * 64 + j * 8 + (lane & 3) * 2 + q;
                    uint u = __float_as_uint(dist);
                    uint m = (u & 0x80000000u) ? ~u : (u | 0x80000000u);
                    ull key = ((ull)(~m) << 32) | (uint)(KCODES - 1 - n);
                    if (key > b1)      { b2 = b1; b1 = key; }
                    else if (key > b2) { b2 = key; }
                }
            }
            #pragma unroll
            for (int sh = 1; sh <= 2; sh <<= 1) {
                ull o1 = __shfl_xor_sync(0xffffffffu, b1, sh);
                ull o2 = __shfl_xor_sync(0xffffffffu, b2, sh);
                ull n1 = umax(b1, o1);
                ull n2 = umax(umin(b1, o1), umax(b2, o2));
                b1 = n1; b2 = n2;
            }
            if ((lane & 3) == 0) {
                sred[(m_local * 2 + wn) * 2 + 0] = b1;
                sred[(m_local * 2 + wn) * 2 + 1] = b2;
            }
        }
    }
    __syncthreads();
    {
        const int row = tid;   // 128 rows, 128 threads
        ull p1a = sred[(row * 2 + 0) * 2 + 0], p2a = sred[(row * 2 + 0) * 2 + 1];
        ull p1b = sred[(row * 2 + 1) * 2 + 0], p2b = sred[(row * 2 + 1) * 2 + 1];
        ull b1 = umax(p1a, p1b);
        ull b2 = umax(umin(p1a, p1b), umax(p2a, p2b));
        g_top1[(ull)(m0 + row) * NSPLITS + nblk] = b1;   // [token][split]
        g_top2[(ull)(m0 + row) * NSPLITS + nblk] = b2;
    }
}

// ---------------------------------------------------------------------------
// K2a: warp-per-token split merge + near-tie exact fp32 fixup (lane-parallel)
// ---------------------------------------------------------------------------
__global__ void k_assign(const float* __restrict__ z, const float* __restrict__ E,
                         float* __restrict__ out) {
    const int gtid = blockIdx.x * 256 + threadIdx.x;
    const int n    = gtid >> 5;          // token = warp
    const int lane = gtid & 31;
    if (n >= NTOK) return;

    const ull* t1p = g_top1 + (ull)n * NSPLITS;
    const ull* t2p = g_top2 + (ull)n * NSPLITS;
    ull b1 = 0ull, b2 = 0ull;
    #pragma unroll
    for (int r = 0; r < 2; r++) {
        int s = lane + r * 32;
        ull t1 = t1p[s], t2 = t2p[s];
        if (t1 > b1)      { b2 = b1; b1 = t1; }
        else if (t1 > b2) { b2 = t1; }
        if (t2 > b2)      { b2 = t2; }
    }
    #pragma unroll
    for (int sh = 16; sh >= 1; sh >>= 1) {
        ull o1 = __shfl_xor_sync(0xffffffffu, b1, sh);
        ull o2 = __shfl_xor_sync(0xffffffffu, b2, sh);
        ull n1 = umax(b1, o1);
        ull n2 = umax(umin(b1, o1), umax(b2, o2));
        b1 = n1; b2 = n2;
    }

    int i1 = (KCODES - 1) - (int)(uint)(b1 & 0xffffffffu);
    int i2 = (KCODES - 1) - (int)(uint)(b2 & 0xffffffffu);
    uint m1 = ~(uint)(b1 >> 32), m2 = ~(uint)(b2 >> 32);
    float d1 = __uint_as_float((m1 & 0x80000000u) ? (m1 & 0x7fffffffu) : ~m1);
    float d2 = __uint_as_float((m2 & 0x80000000u) ? (m2 & 0x7fffffffu) : ~m2);

    int idx = i1;
    if (d2 - d1 < 2e-4f) {
        // exact fp32 re-score, lane-parallel (8 dims/lane), bucketed like ref
        int b = n >> 10, hw = n & 1023;
        const float* zp  = z + b * DD * HW + hw;
        const float* ep1 = E + i1;
        const float* ep2 = E + i2;
        float dot1 = 0.0f, dot2 = 0.0f;
        #pragma unroll
        for (int t = 0; t < 8; t++) {
            int d = t * 32 + lane;
            float zv = zp[d * HW];
            dot1 = fmaf(zv, ep1[d * KCODES], dot1);
            dot2 = fmaf(zv, ep2[d * KCODES], dot2);
        }
        #pragma unroll
        for (int sh = 16; sh >= 1; sh >>= 1) {
            dot1 += __shfl_xor_sync(0xffffffffu, dot1, sh);
            dot2 += __shfl_xor_sync(0xffffffffu, dot2, sh);
        }
        float sx2 = g_sx2[n];
        float e1  = (sx2 - 2.0f * dot1) + g_e2[i1];
        float e2x = (sx2 - 2.0f * dot2) + g_e2[i2];
        if (e2x < e1 || (e2x == e1 && i2 < i1)) idx = i2;
    }
    if (lane == 0) {
        g_idx[n] = idx;
        out[OUT_IDX + n] = (float)idx;
        atomicAdd(&out[OUT_CS + idx], 1.0f);
    }
}

// ---------------------------------------------------------------------------
// K2b: gather quantized (NCHW), scatter dw, accumulate loss; the LAST block
// (ticket) also computes loss + perplexity (cs is complete since k_assign).
// ---------------------------------------------------------------------------
__global__ void k_scatter(const float* __restrict__ z, const float* __restrict__ E,
                          float* __restrict__ out) {
    __shared__ float red[256];
    __shared__ int   s_last;

    int tx = threadIdx.x & 31;
    int ty = threadIdx.x >> 5;
    int hw = blockIdx.x * 32 + tx;
    int d  = blockIdx.y * 8 + ty;
    int b  = blockIdx.z;

    int n   = b * HW + hw;
    int idx = g_idx[n];
    float q  = E[d * KCODES + idx];
    int   zi = (b * DD + d) * HW + hw;
    float zv = z[zi];
    out[OUT_Q + zi] = q;
    float diff = q - zv;
    atomicAdd(&out[OUT_DW + d * KCODES + idx], zv);

    red[threadIdx.x] = diff * diff;
    __syncthreads();
    #pragma unroll
    for (int s = 128; s > 0; s >>= 1) {
        if (threadIdx.x < s) red[threadIdx.x] += red[threadIdx.x + s];
        __syncthreads();
    }
    if (threadIdx.x == 0) atomicAdd(&g_loss, (double)red[0]);
    __threadfence();
    if (threadIdx.x == 0) s_last = atomicAdd(&g_ticket, 1);
    __syncthreads();

    // last block finalizes loss + perplexity
    if (s_last == 8192 - 1) {
        float s = 0.0f;
        for (int k = threadIdx.x; k < KCODES; k += 256) {
            float p = __ldcg(&out[OUT_CS + k]) * (1.0f / 8192.0f);
            s += p * logf(p + 1e-10f);
        }
        red[threadIdx.x] = s;
        __syncthreads();
        #pragma unroll
        for (int st = 128; st > 0; st >>= 1) {
            if (threadIdx.x < st) red[threadIdx.x] += red[threadIdx.x + st];
            __syncthreads();
        }
        if (threadIdx.x == 0) {
            double total = atomicAdd(&g_loss, 0.0);   // atomic read
            out[OUT_PERP] = expf(-red[0]);
            out[OUT_LOSS] = (float)(0.25 * total / 2097152.0);
            g_ticket = 0;
        }
    }
}

// ---------------------------------------------------------------------------
extern "C" void kernel_launch(void* const* d_in, const int* in_sizes, int n_in,
                              void* d_out, int out_size) {
    const float* z = (const float*)d_in[0];         // [8,256,32,32]
    const float* E = (const float*)d_in[1];         // [256,8192]
    float* out = (float*)d_out;

    cudaFuncSetAttribute(k_mma, cudaFuncAttributeMaxDynamicSharedMemorySize,
                         SMEM_DYN);

    k_prep   <<< 512, 256 >>>(z, E, out);
    k_mma    <<< dim3(NTOK / MTILE, NSPLITS), 128, SMEM_DYN >>>();
    k_assign <<< (NTOK * 32) / 256, 256 >>>(z, E, out);
    k_scatter<<< dim3(HW / 32, DD / 8, BATCH), 256 >>>(z, E, out);
}

// round 13
// speedup vs baseline: 1.0983x; 1.0343x over previous
#include <cuda_runtime.h>
#include <cuda_bf16.h>
#include <math.h>

// Problem constants
#define DD      256
#define KCODES  8192
#define BATCH   8
#define HW      1024
#define NTOK    8192

// Output layout (flattened return tuple, in order)
#define OUT_Q     0
#define OUT_LOSS  2097152
#define OUT_PERP  2097153
#define OUT_IDX   2097154
#define OUT_DW    2105346
#define OUT_CS    4202498

// GEMM config: C[8192 tok, 8192 codes] = A[.,768] * B[.,768]^T  (bf16x3 split)
#define KTOT    768
#define MTILE   128
#define NTILE   128
#define KS      64
#define NSTAGES 12                    // 768/64
#define NPIPE   3                     // cp.async pipeline depth
#define NSPLITS (KCODES / NTILE)      // 64
#define ABYTES  16384                 // per-stage A buffer (128 x 128B)
#define BBYTES  16384                 // per-stage B buffer
#define SM_RED  (NPIPE * (ABYTES + BBYTES))    // 98304: sred after tiles
#define SMEM_DYN (SM_RED + 4096)               // 100KB/CTA -> 2 CTAs/SM

typedef unsigned long long ull;
typedef unsigned int uint;

// ---------------- device scratch (no allocation allowed) --------------------
__device__ __nv_bfloat16 g_A[NTOK   * KTOT];  // [tok ][xh(256)|xh(256)|xl(256)]
__device__ __nv_bfloat16 g_B[KCODES * KTOT];  // [code][eh(256)|el(256)|eh(256)]
__device__ float  g_e2[KCODES];
__device__ float  g_sx2[NTOK];
__device__ ull    g_top1[NTOK * NSPLITS];     // [token][split]  (coalesced merge)
__device__ ull    g_top2[NTOK * NSPLITS];
__device__ int    g_idx[NTOK];
__device__ double g_loss;

// ---------------- PTX helpers (all plain-sm_100 legal) ----------------------
__device__ __forceinline__ uint smem_u32(const void* p) {
    uint a;
    asm("{ .reg .u64 t; cvta.to.shared.u64 t, %1; cvt.u32.u64 %0, t; }"
        : "=r"(a) : "l"(p));
    return a;
}
#define CP16(dst, src) \
    asm volatile("cp.async.cg.shared.global [%0], [%1], 16;" :: "r"(dst), "l"(src))
#define CP_COMMIT() asm volatile("cp.async.commit_group;")
#define CP_WAIT(n)  asm volatile("cp.async.wait_group %0;" :: "n"(n))

#define LDSM4(r0, r1, r2, r3, a) \
    asm volatile("ldmatrix.sync.aligned.m8n8.x4.shared.b16 {%0,%1,%2,%3}, [%4];" \
        : "=r"(r0), "=r"(r1), "=r"(r2), "=r"(r3) : "r"(a))

#define MMA16816(c, a, b) \
    asm volatile("mma.sync.aligned.m16n8k16.row.col.f32.bf16.bf16.f32 " \
        "{%0,%1,%2,%3}, {%4,%5,%6,%7}, {%8,%9}, {%0,%1,%2,%3};" \
        : "+f"((c)[0]), "+f"((c)[1]), "+f"((c)[2]), "+f"((c)[3]) \
        : "r"((a)[0]), "r"((a)[1]), "r"((a)[2]), "r"((a)[3]), \
          "r"((b)[0]), "r"((b)[1]))

__device__ __forceinline__ ull umax(ull a, ull b) { return a > b ? a : b; }
__device__ __forceinline__ ull umin(ull a, ull b) { return a < b ? a : b; }

// ---------------------------------------------------------------------------
// K_prep (fused init + norms + transpose/split, vectorized bf16 stores):
//   Blocks 0..255:   z -> g_A (32 tokens each) + g_sx2
//   Blocks 256..511: E -> g_B (32 codes each)  + g_e2
// ---------------------------------------------------------------------------
__global__ void k_prep(const float* __restrict__ z, const float* __restrict__ E,
                       float* __restrict__ out) {
    __shared__ float st[32 * 264];
    const int tid = threadIdx.x;
    const bool isB = blockIdx.x >= 256;
    const int n0 = (isB ? (blockIdx.x - 256) : blockIdx.x) * 32;

    // zero dw + cluster_size (2105344 floats = 1052672 float2, 8B-aligned)
    {
        const float2 z2 = make_float2(0.0f, 0.0f);
        float2* dst2 = (float2*)(out + OUT_DW);
        for (int i = blockIdx.x * 256 + tid; i < 1052672; i += 512 * 256)
            dst2[i] = z2;
        if (blockIdx.x == 0 && tid == 0) g_loss = 0.0;
    }

    // load 32 rows x 256 dims into smem (transposed)
    for (int i = tid; i < 32 * 256; i += 256) {
        int k = i >> 5, nl = i & 31;
        float v;
        if (isB) v = E[k * KCODES + n0 + nl];
        else {
            int b = n0 >> 10, hw0 = n0 & 1023;
            v = z[(b * DD + k) * HW + hw0 + nl];
        }
        st[nl * 264 + k] = v;
    }
    __syncthreads();

    // norms: one thread per row, sequential fp32 over d (bit-identical path)
    if (tid < 32) {
        float s = 0.0f;
        #pragma unroll 8
        for (int d = 0; d < DD; d++) { float v = st[tid * 264 + d]; s += v * v; }
        if (isB) g_e2[n0 + tid] = s;
        else     g_sx2[n0 + tid] = s;
    }

    // bf16 hi/lo split, packed stores:  A row [xh|xh|xl],  B row [eh|el|eh]
    __nv_bfloat16* dst = isB ? g_B : g_A;
    const int nl = tid >> 3;
    const int jb = (tid & 7) * 32;
    __nv_bfloat16* rowp = dst + (ull)(n0 + nl) * KTOT;

    uint hwv[16], lwv[16];
    #pragma unroll
    for (int t = 0; t < 16; t++) {
        float v0 = st[nl * 264 + jb + 2 * t];
        float v1 = st[nl * 264 + jb + 2 * t + 1];
        __nv_bfloat16 h0 = __float2bfloat16(v0);
        __nv_bfloat16 h1 = __float2bfloat16(v1);
        __nv_bfloat16 l0 = __float2bfloat16(v0 - __bfloat162float(h0));
        __nv_bfloat16 l1 = __float2bfloat16(v1 - __bfloat162float(h1));
        hwv[t] = (uint)__bfloat16_as_ushort(h0) | ((uint)__bfloat16_as_ushort(h1) << 16);
        lwv[t] = (uint)__bfloat16_as_ushort(l0) | ((uint)__bfloat16_as_ushort(l1) << 16);
    }
    uint4* p0 = (uint4*)(rowp + jb);            // hi
    uint4* p1 = (uint4*)(rowp + 256 + jb);      // B: lo,  A: hi
    uint4* p2 = (uint4*)(rowp + 512 + jb);      // B: hi,  A: lo
    #pragma unroll
    for (int t = 0; t < 4; t++) {
        uint4 hv = make_uint4(hwv[4*t], hwv[4*t+1], hwv[4*t+2], hwv[4*t+3]);
        uint4 lv = make_uint4(lwv[4*t], lwv[4*t+1], lwv[4*t+2], lwv[4*t+3]);
        p0[t] = hv;
        p1[t] = isB ? lv : hv;
        p2[t] = isB ? hv : lv;
    }
}

// ---------------------------------------------------------------------------
// K1: HMMA bf16 distance GEMM fused with per-token top-2 (R9 config, best
// measured). CTA tile 128x128, 4 warps (2m x 2n), warp tile 64x64, NPIPE=3,
// 100KB smem -> 2 CTAs/SM. Grid (64 m-tiles, 64 n-blocks).
// ---------------------------------------------------------------------------
__global__ void __launch_bounds__(128, 2)
k_mma() {
    extern __shared__ char smem[];
    const uint sb  = smem_u32(smem);
    const uint sA  = sb;                       // 3 x 16KB
    const uint sB  = sb + NPIPE * ABYTES;      // 3 x 16KB
    ull* sred = (ull*)(smem + SM_RED);         // 4KB, separate from tiles

    const int tid  = threadIdx.x;
    const int lane = tid & 31;
    const int wid  = tid >> 5;      // 0..3
    const int wm   = wid & 1;       // m warp (2): 64 rows each
    const int wn   = wid >> 1;      // n warp (2): 64 cols each

    const int m0   = blockIdx.x * MTILE;
    const int nblk = blockIdx.y;
    const int n0   = nblk * NTILE;

    const __nv_bfloat16* gA = g_A + (ull)m0 * KTOT;
    const __nv_bfloat16* gB = g_B + (ull)n0 * KTOT;

    float c[4][8][4];
    #pragma unroll
    for (int i = 0; i < 4; i++)
        #pragma unroll
        for (int j = 0; j < 8; j++)
            #pragma unroll
            for (int r = 0; r < 4; r++) c[i][j][r] = 0.0f;

    // --- hoisted issue-side address components (tid-constant) ---
    const int ld_row = tid >> 3;           // 0..15
    const int ld_ch  = tid & 7;
    const uint ld_sw = (uint)((ld_ch ^ (ld_row & 7)) << 4);
    const uint dst_base = (uint)ld_row * 128u + ld_sw;
    const __nv_bfloat16* srcA0 = gA + (ull)ld_row * KTOT + ld_ch * 8;
    const __nv_bfloat16* srcB0 = gB + (ull)ld_row * KTOT + ld_ch * 8;

    // --- hoisted ldmatrix address components ---
    const int rowA = wm * 64 + (lane & 7) + ((lane >> 3) & 1) * 8;  // + i*16
    const int chA  = (lane >> 4);
    const int rowB = wn * 64 + (lane & 7) + ((lane >> 4) << 3);     // + nb*16
    const int chB  = (lane >> 3) & 1;
    uint colA[4], colB[4];
    #pragma unroll
    for (int ks = 0; ks < 4; ks++) {
        colA[ks] = (uint)(((ks * 2 + chA) ^ (rowA & 7)) << 4);
        colB[ks] = (uint)(((ks * 2 + chB) ^ (rowB & 7)) << 4);
    }
    uint rbaseA[4], rbaseB[4];
    #pragma unroll
    for (int i = 0; i < 4; i++) rbaseA[i] = (uint)(rowA + i * 16) * 128u;
    #pragma unroll
    for (int i = 0; i < 4; i++) rbaseB[i] = (uint)(rowB + i * 16) * 128u;

    // stage issuer: 8 A-chunks + 8 B-chunks of 16B per thread (128 threads)
    auto issue = [&](int s, int buf) {
        const int kb = s * KS;
        const uint bufA = sA + (uint)buf * ABYTES;
        const uint bufB = sB + (uint)buf * BBYTES;
        const __nv_bfloat16* sa  = srcA0 + kb;
        const __nv_bfloat16* sbp = srcB0 + kb;
        #pragma unroll
        for (int i = 0; i < 8; i++)
            CP16(bufA + dst_base + (uint)i * 2048u, sa + (ull)i * 16 * KTOT);
        #pragma unroll
        for (int i = 0; i < 8; i++)
            CP16(bufB + dst_base + (uint)i * 2048u, sbp + (ull)i * 16 * KTOT);
        CP_COMMIT();
    };

    issue(0, 0); issue(1, 1);

    int buf = 0;
    for (int s = 0; s < NSTAGES; s++) {
        if (s < NSTAGES - 1) { CP_WAIT(1); } else { CP_WAIT(0); }
        __syncthreads();

        const uint bufA = sA + (uint)buf * ABYTES;
        const uint bufB = sB + (uint)buf * BBYTES;

        #pragma unroll
        for (int ks = 0; ks < 4; ks++) {
            uint a[4][4];
            #pragma unroll
            for (int i = 0; i < 4; i++)
                LDSM4(a[i][0], a[i][1], a[i][2], a[i][3],
                      bufA + rbaseA[i] + colA[ks]);
            uint b[8][2];
            #pragma unroll
            for (int nb = 0; nb < 4; nb++) {
                uint r0, r1, r2, r3;
                LDSM4(r0, r1, r2, r3, bufB + rbaseB[nb] + colB[ks]);
                b[nb * 2][0] = r0;     b[nb * 2][1] = r1;
                b[nb * 2 + 1][0] = r2; b[nb * 2 + 1][1] = r3;
            }
            #pragma unroll
            for (int i = 0; i < 4; i++)
                #pragma unroll
                for (int j = 0; j < 8; j++)
                    MMA16816(c[i][j], a[i], b[j]);
        }
        if (s + 2 < NSTAGES) {
            int nbuf = buf + 2; if (nbuf >= NPIPE) nbuf -= NPIPE;
            issue(s + 2, nbuf);
        }
        if (++buf == NPIPE) buf = 0;
    }

    // ---------------- epilogue: dist + top-2, no atomics --------------------
    float e2v[8][2];
    #pragma unroll
    for (int j = 0; j < 8; j++)
        #pragma unroll
        for (int q = 0; q < 2; q++)
            e2v[j][q] = g_e2[n0 + wn * 64 + j * 8 + (lane & 3) * 2 + q];

    #pragma unroll
    for (int i = 0; i < 4; i++) {
        #pragma unroll
        for (int h = 0; h < 2; h++) {
            const int m_local = wm * 64 + i * 16 + (lane >> 2) + h * 8;
            const float sx2 = g_sx2[m0 + m_local];
            ull b1 = 0ull, b2 = 0ull;
            #pragma unroll
            for (int j = 0; j < 8; j++) {
                #pragma unroll
                for (int q = 0; q < 2; q++) {
                    float dot  = c[i][j][h * 2 + q];
                    float dist = (sx2 - 2.0f * dot) + e2v[j][q];
                    const int n = n0 + wn * 64 + j * 8 + (lane & 3) * 2 + q;
                    uint u = __float_as_uint(dist);
                    uint m = (u & 0x80000000u) ? ~u : (u | 0x80000000u);
                    ull key = ((ull)(~m) << 32) | (uint)(KCODES - 1 - n);
                    if (key > b1)      { b2 = b1; b1 = key; }
                    else if (key > b2) { b2 = key; }
                }
            }
            #pragma unroll
            for (int sh = 1; sh <= 2; sh <<= 1) {
                ull o1 = __shfl_xor_sync(0xffffffffu, b1, sh);
                ull o2 = __shfl_xor_sync(0xffffffffu, b2, sh);
                ull n1 = umax(b1, o1);
                ull n2 = umax(umin(b1, o1), umax(b2, o2));
                b1 = n1; b2 = n2;
            }
            if ((lane & 3) == 0) {
                sred[(m_local * 2 + wn) * 2 + 0] = b1;
                sred[(m_local * 2 + wn) * 2 + 1] = b2;
            }
        }
    }
    __syncthreads();
    {
        const int row = tid;   // 128 rows, 128 threads
        ull p1a = sred[(row * 2 + 0) * 2 + 0], p2a = sred[(row * 2 + 0) * 2 + 1];
        ull p1b = sred[(row * 2 + 1) * 2 + 0], p2b = sred[(row * 2 + 1) * 2 + 1];
        ull b1 = umax(p1a, p1b);
        ull b2 = umax(umin(p1a, p1b), umax(p2a, p2b));
        g_top1[(ull)(m0 + row) * NSPLITS + nblk] = b1;   // [token][split]
        g_top2[(ull)(m0 + row) * NSPLITS + nblk] = b2;
    }
}

// ---------------------------------------------------------------------------
// K2a: warp-per-token split merge + near-tie exact fp32 fixup (lane-parallel)
// ---------------------------------------------------------------------------
__global__ void k_assign(const float* __restrict__ z, const float* __restrict__ E,
                         float* __restrict__ out) {
    const int gtid = blockIdx.x * 256 + threadIdx.x;
    const int n    = gtid >> 5;          // token = warp
    const int lane = gtid & 31;
    if (n >= NTOK) return;

    const ull* t1p = g_top1 + (ull)n * NSPLITS;
    const ull* t2p = g_top2 + (ull)n * NSPLITS;
    ull b1 = 0ull, b2 = 0ull;
    #pragma unroll
    for (int r = 0; r < 2; r++) {
        int s = lane + r * 32;
        ull t1 = t1p[s], t2 = t2p[s];
        if (t1 > b1)      { b2 = b1; b1 = t1; }
        else if (t1 > b2) { b2 = t1; }
        if (t2 > b2)      { b2 = t2; }
    }
    #pragma unroll
    for (int sh = 16; sh >= 1; sh >>= 1) {
        ull o1 = __shfl_xor_sync(0xffffffffu, b1, sh);
        ull o2 = __shfl_xor_sync(0xffffffffu, b2, sh);
        ull n1 = umax(b1, o1);
        ull n2 = umax(umin(b1, o1), umax(b2, o2));
        b1 = n1; b2 = n2;
    }

    int i1 = (KCODES - 1) - (int)(uint)(b1 & 0xffffffffu);
    int i2 = (KCODES - 1) - (int)(uint)(b2 & 0xffffffffu);
    uint m1 = ~(uint)(b1 >> 32), m2 = ~(uint)(b2 >> 32);
    float d1 = __uint_as_float((m1 & 0x80000000u) ? (m1 & 0x7fffffffu) : ~m1);
    float d2 = __uint_as_float((m2 & 0x80000000u) ? (m2 & 0x7fffffffu) : ~m2);

    int idx = i1;
    if (d2 - d1 < 2e-4f) {
        // exact fp32 re-score, lane-parallel (8 dims/lane), bucketed like ref
        int b = n >> 10, hw = n & 1023;
        const float* zp  = z + b * DD * HW + hw;
        const float* ep1 = E + i1;
        const float* ep2 = E + i2;
        float dot1 = 0.0f, dot2 = 0.0f;
        #pragma unroll
        for (int t = 0; t < 8; t++) {
            int d = t * 32 + lane;
            float zv = zp[d * HW];
            dot1 = fmaf(zv, ep1[d * KCODES], dot1);
            dot2 = fmaf(zv, ep2[d * KCODES], dot2);
        }
        #pragma unroll
        for (int sh = 16; sh >= 1; sh >>= 1) {
            dot1 += __shfl_xor_sync(0xffffffffu, dot1, sh);
            dot2 += __shfl_xor_sync(0xffffffffu, dot2, sh);
        }
        float sx2 = g_sx2[n];
        float e1  = (sx2 - 2.0f * dot1) + g_e2[i1];
        float e2x = (sx2 - 2.0f * dot2) + g_e2[i2];
        if (e2x < e1 || (e2x == e1 && i2 < i1)) idx = i2;
    }
    if (lane == 0) {
        g_idx[n] = idx;
        out[OUT_IDX + n] = (float)idx;
        atomicAdd(&out[OUT_CS + idx], 1.0f);
    }
}

// ---------------------------------------------------------------------------
// K2b: gather quantized (NCHW), scatter dw, accumulate loss. Vectorized:
// each thread handles 4 consecutive hw (float4 z read / Q write, int4 idx).
// grid (HW/128=8, DD/8=32, 8) = 2048 blocks, 256 threads.
// ---------------------------------------------------------------------------
__global__ void k_scatter(const float* __restrict__ z, const float* __restrict__ E,
                          float* __restrict__ out) {
    __shared__ float red[256];

    int tx  = threadIdx.x & 31;          // hw quad
    int ty  = threadIdx.x >> 5;          // d
    int hw4 = blockIdx.x * 128 + tx * 4;
    int d   = blockIdx.y * 8 + ty;
    int b   = blockIdx.z;

    int nb = b * HW + hw4;
    int4 idx4 = *(const int4*)&g_idx[nb];
    const float* Ed = E + (ull)d * KCODES;
    float q0 = Ed[idx4.x], q1 = Ed[idx4.y], q2 = Ed[idx4.z], q3 = Ed[idx4.w];

    int zi = (b * DD + d) * HW + hw4;
    float4 zv = *(const float4*)&z[zi];
    *(float4*)&out[OUT_Q + zi] = make_float4(q0, q1, q2, q3);

    float* dwd = out + OUT_DW + (ull)d * KCODES;
    atomicAdd(&dwd[idx4.x], zv.x);
    atomicAdd(&dwd[idx4.y], zv.y);
    atomicAdd(&dwd[idx4.z], zv.z);
    atomicAdd(&dwd[idx4.w], zv.w);

    float d0 = q0 - zv.x, d1 = q1 - zv.y, d2 = q2 - zv.z, d3 = q3 - zv.w;
    red[threadIdx.x] = d0 * d0 + d1 * d1 + d2 * d2 + d3 * d3;
    __syncthreads();
    #pragma unroll
    for (int s = 128; s > 0; s >>= 1) {
        if (threadIdx.x < s) red[threadIdx.x] += red[threadIdx.x + s];
        __syncthreads();
    }
    if (threadIdx.x == 0) atomicAdd(&g_loss, (double)red[0]);
}

// ---------------------------------------------------------------------------
// K3: loss + perplexity
// ---------------------------------------------------------------------------
__global__ void k_final(float* __restrict__ out) {
    __shared__ float red[256];
    int t = threadIdx.x;
    float s = 0.0f;
    for (int k = t; k < KCODES; k += 256) {
        float p = out[OUT_CS + k] * (1.0f / 8192.0f);
        s += p * logf(p + 1e-10f);
    }
    red[t] = s;
    __syncthreads();
    #pragma unroll
    for (int st = 128; st > 0; st >>= 1) {
        if (t < st) red[t] += red[t + st];
        __syncthreads();
    }
    if (t == 0) {
        out[OUT_PERP] = expf(-red[0]);
        out[OUT_LOSS] = (float)(0.25 * g_loss / 2097152.0);
    }
}

// ---------------------------------------------------------------------------
extern "C" void kernel_launch(void* const* d_in, const int* in_sizes, int n_in,
                              void* d_out, int out_size) {
    const float* z = (const float*)d_in[0];         // [8,256,32,32]
    const float* E = (const float*)d_in[1];         // [256,8192]
    float* out = (float*)d_out;

    cudaFuncSetAttribute(k_mma, cudaFuncAttributeMaxDynamicSharedMemorySize,
                         SMEM_DYN);

    k_prep   <<< 512, 256 >>>(z, E, out);
    k_mma    <<< dim3(NTOK / MTILE, NSPLITS), 128, SMEM_DYN >>>();
    k_assign <<< (NTOK * 32) / 256, 256 >>>(z, E, out);
    k_scatter<<< dim3(HW / 128, DD / 8, BATCH), 256 >>>(z, E, out);
    k_final  <<< 1, 256 >>>(out);
}

// round 14
// speedup vs baseline: 1.1053x; 1.0063x over previous
#include <cuda_runtime.h>
#include <cuda_bf16.h>
#include <math.h>

// Problem constants
#define DD      256
#define KCODES  8192
#define BATCH   8
#define HW      1024
#define NTOK    8192

// Output layout (flattened return tuple, in order)
#define OUT_Q     0
#define OUT_LOSS  2097152
#define OUT_PERP  2097153
#define OUT_IDX   2097154
#define OUT_DW    2105346
#define OUT_CS    4202498

// GEMM config: C[8192 tok, 8192 codes] = A[.,768] * B[.,768]^T  (bf16x3 split)
#define KTOT    768
#define MTILE   128
#define NTILE   128
#define KS      64
#define NSTAGES 12                    // 768/64
#define NPIPE   3                     // cp.async pipeline depth
#define NSPLITS (KCODES / NTILE)      // 64
#define ABYTES  16384                 // per-stage A buffer (128 x 128B)
#define BBYTES  16384                 // per-stage B buffer
#define SM_RED  (NPIPE * (ABYTES + BBYTES))    // 98304: sred after tiles
#define SMEM_DYN (SM_RED + 4096)               // 100KB/CTA -> 2 CTAs/SM

#define PREP_PAD 257                  // stride mod 32 == 1 -> conflict-free

typedef unsigned long long ull;
typedef unsigned int uint;

// ---------------- device scratch (no allocation allowed) --------------------
__device__ __nv_bfloat16 g_A[NTOK   * KTOT];  // [tok ][xh(256)|xh(256)|xl(256)]
__device__ __nv_bfloat16 g_B[KCODES * KTOT];  // [code][eh(256)|el(256)|eh(256)]
__device__ float  g_e2[KCODES];
__device__ float  g_sx2[NTOK];
__device__ ull    g_top1[NTOK * NSPLITS];     // [token][split]  (coalesced merge)
__device__ ull    g_top2[NTOK * NSPLITS];
__device__ int    g_idx[NTOK];
__device__ double g_loss;

// ---------------- PTX helpers (all plain-sm_100 legal) ----------------------
__device__ __forceinline__ uint smem_u32(const void* p) {
    uint a;
    asm("{ .reg .u64 t; cvta.to.shared.u64 t, %1; cvt.u32.u64 %0, t; }"
        : "=r"(a) : "l"(p));
    return a;
}
#define CP16(dst, src) \
    asm volatile("cp.async.cg.shared.global [%0], [%1], 16;" :: "r"(dst), "l"(src))
#define CP_COMMIT() asm volatile("cp.async.commit_group;")
#define CP_WAIT(n)  asm volatile("cp.async.wait_group %0;" :: "n"(n))

#define LDSM4(r0, r1, r2, r3, a) \
    asm volatile("ldmatrix.sync.aligned.m8n8.x4.shared.b16 {%0,%1,%2,%3}, [%4];" \
        : "=r"(r0), "=r"(r1), "=r"(r2), "=r"(r3) : "r"(a))

#define MMA16816(c, a, b) \
    asm volatile("mma.sync.aligned.m16n8k16.row.col.f32.bf16.bf16.f32 " \
        "{%0,%1,%2,%3}, {%4,%5,%6,%7}, {%8,%9}, {%0,%1,%2,%3};" \
        : "+f"((c)[0]), "+f"((c)[1]), "+f"((c)[2]), "+f"((c)[3]) \
        : "r"((a)[0]), "r"((a)[1]), "r"((a)[2]), "r"((a)[3]), \
          "r"((b)[0]), "r"((b)[1]))

__device__ __forceinline__ ull umax(ull a, ull b) { return a > b ? a : b; }
__device__ __forceinline__ ull umin(ull a, ull b) { return a < b ? a : b; }

// ---------------------------------------------------------------------------
// K_prep (fused init + norms + transpose/split). Conflict-free smem:
// pad 257 (stride%32==1), split loop row = tid&31 so a warp spans 32 rows.
//   Blocks 0..255:   z -> g_A (32 tokens each) + g_sx2
//   Blocks 256..511: E -> g_B (32 codes each)  + g_e2
// ---------------------------------------------------------------------------
__global__ void k_prep(const float* __restrict__ z, const float* __restrict__ E,
                       float* __restrict__ out) {
    __shared__ float st[32 * PREP_PAD];
    const int tid = threadIdx.x;
    const bool isB = blockIdx.x >= 256;
    const int n0 = (isB ? (blockIdx.x - 256) : blockIdx.x) * 32;

    // zero dw + cluster_size (2105344 floats = 1052672 float2, 8B-aligned)
    {
        const float2 z2 = make_float2(0.0f, 0.0f);
        float2* dst2 = (float2*)(out + OUT_DW);
        for (int i = blockIdx.x * 256 + tid; i < 1052672; i += 512 * 256)
            dst2[i] = z2;
        if (blockIdx.x == 0 && tid == 0) g_loss = 0.0;
    }

    // load 32 rows x 256 dims into smem (transposed); stride 257 -> no conflicts
    for (int i = tid; i < 32 * 256; i += 256) {
        int k = i >> 5, nl = i & 31;
        float v;
        if (isB) v = E[k * KCODES + n0 + nl];
        else {
            int b = n0 >> 10, hw0 = n0 & 1023;
            v = z[(b * DD + k) * HW + hw0 + nl];
        }
        st[nl * PREP_PAD + k] = v;
    }
    __syncthreads();

    // norms: one thread per row, sequential fp32 over d (bit-identical path)
    if (tid < 32) {
        float s = 0.0f;
        #pragma unroll 8
        for (int d = 0; d < DD; d++) { float v = st[tid * PREP_PAD + d]; s += v * v; }
        if (isB) g_e2[n0 + tid] = s;
        else     g_sx2[n0 + tid] = s;
    }

    // bf16 hi/lo split, packed stores:  A row [xh|xh|xl],  B row [eh|el|eh]
    // row = tid&31 (warp spans 32 rows -> conflict-free smem reads),
    // chunk jb = (tid>>5)*32 (8 chunks of 32 values).
    __nv_bfloat16* dst = isB ? g_B : g_A;
    const int nl = tid & 31;
    const int jb = (tid >> 5) * 32;
    __nv_bfloat16* rowp = dst + (ull)(n0 + nl) * KTOT;

    uint hwv[16], lwv[16];
    #pragma unroll
    for (int t = 0; t < 16; t++) {
        float v0 = st[nl * PREP_PAD + jb + 2 * t];
        float v1 = st[nl * PREP_PAD + jb + 2 * t + 1];
        __nv_bfloat16 h0 = __float2bfloat16(v0);
        __nv_bfloat16 h1 = __float2bfloat16(v1);
        __nv_bfloat16 l0 = __float2bfloat16(v0 - __bfloat162float(h0));
        __nv_bfloat16 l1 = __float2bfloat16(v1 - __bfloat162float(h1));
        hwv[t] = (uint)__bfloat16_as_ushort(h0) | ((uint)__bfloat16_as_ushort(h1) << 16);
        lwv[t] = (uint)__bfloat16_as_ushort(l0) | ((uint)__bfloat16_as_ushort(l1) << 16);
    }
    uint4* p0 = (uint4*)(rowp + jb);            // hi
    uint4* p1 = (uint4*)(rowp + 256 + jb);      // B: lo,  A: hi
    uint4* p2 = (uint4*)(rowp + 512 + jb);      // B: hi,  A: lo
    #pragma unroll
    for (int t = 0; t < 4; t++) {
        uint4 hv = make_uint4(hwv[4*t], hwv[4*t+1], hwv[4*t+2], hwv[4*t+3]);
        uint4 lv = make_uint4(lwv[4*t], lwv[4*t+1], lwv[4*t+2], lwv[4*t+3]);
        p0[t] = hv;
        p1[t] = isB ? lv : hv;
        p2[t] = isB ? hv : lv;
    }
}

// ---------------------------------------------------------------------------
// K1: HMMA bf16 distance GEMM fused with per-token top-2 (R9 config, best
// measured). CTA tile 128x128, 4 warps (2m x 2n), warp tile 64x64, NPIPE=3,
// 100KB smem -> 2 CTAs/SM. Grid (64 m-tiles, 64 n-blocks).
// ---------------------------------------------------------------------------
__global__ void __launch_bounds__(128, 2)
k_mma() {
    extern __shared__ char smem[];
    const uint sb  = smem_u32(smem);
    const uint sA  = sb;                       // 3 x 16KB
    const uint sB  = sb + NPIPE * ABYTES;      // 3 x 16KB
    ull* sred = (ull*)(smem + SM_RED);         // 4KB, separate from tiles

    const int tid  = threadIdx.x;
    const int lane = tid & 31;
    const int wid  = tid >> 5;      // 0..3
    const int wm   = wid & 1;       // m warp (2): 64 rows each
    const int wn   = wid >> 1;      // n warp (2): 64 cols each

    const int m0   = blockIdx.x * MTILE;
    const int nblk = blockIdx.y;
    const int n0   = nblk * NTILE;

    const __nv_bfloat16* gA = g_A + (ull)m0 * KTOT;
    const __nv_bfloat16* gB = g_B + (ull)n0 * KTOT;

    float c[4][8][4];
    #pragma unroll
    for (int i = 0; i < 4; i++)
        #pragma unroll
        for (int j = 0; j < 8; j++)
            #pragma unroll
            for (int r = 0; r < 4; r++) c[i][j][r] = 0.0f;

    // --- hoisted issue-side address components (tid-constant) ---
    const int ld_row = tid >> 3;           // 0..15
    const int ld_ch  = tid & 7;
    const uint ld_sw = (uint)((ld_ch ^ (ld_row & 7)) << 4);
    const uint dst_base = (uint)ld_row * 128u + ld_sw;
    const __nv_bfloat16* srcA0 = gA + (ull)ld_row * KTOT + ld_ch * 8;
    const __nv_bfloat16* srcB0 = gB + (ull)ld_row * KTOT + ld_ch * 8;

    // --- hoisted ldmatrix address components ---
    const int rowA = wm * 64 + (lane & 7) + ((lane >> 3) & 1) * 8;  // + i*16
    const int chA  = (lane >> 4);
    const int rowB = wn * 64 + (lane & 7) + ((lane >> 4) << 3);     // + nb*16
    const int chB  = (lane >> 3) & 1;
    uint colA[4], colB[4];
    #pragma unroll
    for (int ks = 0; ks < 4; ks++) {
        colA[ks] = (uint)(((ks * 2 + chA) ^ (rowA & 7)) << 4);
        colB[ks] = (uint)(((ks * 2 + chB) ^ (rowB & 7)) << 4);
    }
    uint rbaseA[4], rbaseB[4];
    #pragma unroll
    for (int i = 0; i < 4; i++) rbaseA[i] = (uint)(rowA + i * 16) * 128u;
    #pragma unroll
    for (int i = 0; i < 4; i++) rbaseB[i] = (uint)(rowB + i * 16) * 128u;

    // stage issuer: 8 A-chunks + 8 B-chunks of 16B per thread (128 threads)
    auto issue = [&](int s, int buf) {
        const int kb = s * KS;
        const uint bufA = sA + (uint)buf * ABYTES;
        const uint bufB = sB + (uint)buf * BBYTES;
        const __nv_bfloat16* sa  = srcA0 + kb;
        const __nv_bfloat16* sbp = srcB0 + kb;
        #pragma unroll
        for (int i = 0; i < 8; i++)
            CP16(bufA + dst_base + (uint)i * 2048u, sa + (ull)i * 16 * KTOT);
        #pragma unroll
        for (int i = 0; i < 8; i++)
            CP16(bufB + dst_base + (uint)i * 2048u, sbp + (ull)i * 16 * KTOT);
        CP_COMMIT();
    };

    issue(0, 0); issue(1, 1);

    int buf = 0;
    for (int s = 0; s < NSTAGES; s++) {
        if (s < NSTAGES - 1) { CP_WAIT(1); } else { CP_WAIT(0); }
        __syncthreads();

        const uint bufA = sA + (uint)buf * ABYTES;
        const uint bufB = sB + (uint)buf * BBYTES;

        #pragma unroll
        for (int ks = 0; ks < 4; ks++) {
            uint a[4][4];
            #pragma unroll
            for (int i = 0; i < 4; i++)
                LDSM4(a[i][0], a[i][1], a[i][2], a[i][3],
                      bufA + rbaseA[i] + colA[ks]);
            uint b[8][2];
            #pragma unroll
            for (int nb = 0; nb < 4; nb++) {
                uint r0, r1, r2, r3;
                LDSM4(r0, r1, r2, r3, bufB + rbaseB[nb] + colB[ks]);
                b[nb * 2][0] = r0;     b[nb * 2][1] = r1;
                b[nb * 2 + 1][0] = r2; b[nb * 2 + 1][1] = r3;
            }
            #pragma unroll
            for (int i = 0; i < 4; i++)
                #pragma unroll
                for (int j = 0; j < 8; j++)
                    MMA16816(c[i][j], a[i], b[j]);
        }
        if (s + 2 < NSTAGES) {
            int nbuf = buf + 2; if (nbuf >= NPIPE) nbuf -= NPIPE;
            issue(s + 2, nbuf);
        }
        if (++buf == NPIPE) buf = 0;
    }

    // ---------------- epilogue: dist + top-2, no atomics --------------------
    float e2v[8][2];
    #pragma unroll
    for (int j = 0; j < 8; j++)
        #pragma unroll
        for (int q = 0; q < 2; q++)
            e2v[j][q] = g_e2[n0 + wn * 64 + j * 8 + (lane & 3) * 2 + q];

    #pragma unroll
    for (int i = 0; i < 4; i++) {
        #pragma unroll
        for (int h = 0; h < 2; h++) {
            const int m_local = wm * 64 + i * 16 + (lane >> 2) + h * 8;
            const float sx2 = g_sx2[m0 + m_local];
            ull b1 = 0ull, b2 = 0ull;
            #pragma unroll
            for (int j = 0; j < 8; j++) {
                #pragma unroll
                for (int q = 0; q < 2; q++) {
                    float dot  = c[i][j][h * 2 + q];
                    float dist = (sx2 - 2.0f * dot) + e2v[j][q];
                    const int n = n0 + wn * 64 + j * 8 + (lane & 3) * 2 + q;
                    uint u = __float_as_uint(dist);
                    uint m = (u & 0x80000000u) ? ~u : (u | 0x80000000u);
                    ull key = ((ull)(~m) << 32) | (uint)(KCODES - 1 - n);
                    if (key > b1)      { b2 = b1; b1 = key; }
                    else if (key > b2) { b2 = key; }
                }
            }
            #pragma unroll
            for (int sh = 1; sh <= 2; sh <<= 1) {
                ull o1 = __shfl_xor_sync(0xffffffffu, b1, sh);
                ull o2 = __shfl_xor_sync(0xffffffffu, b2, sh);
                ull n1 = umax(b1, o1);
                ull n2 = umax(umin(b1, o1), umax(b2, o2));
                b1 = n1; b2 = n2;
            }
            if ((lane & 3) == 0) {
                sred[(m_local * 2 + wn) * 2 + 0] = b1;
                sred[(m_local * 2 + wn) * 2 + 1] = b2;
            }
        }
    }
    __syncthreads();
    {
        const int row = tid;   // 128 rows, 128 threads
        ull p1a = sred[(row * 2 + 0) * 2 + 0], p2a = sred[(row * 2 + 0) * 2 + 1];
        ull p1b = sred[(row * 2 + 1) * 2 + 0], p2b = sred[(row * 2 + 1) * 2 + 1];
        ull b1 = umax(p1a, p1b);
        ull b2 = umax(umin(p1a, p1b), umax(p2a, p2b));
        g_top1[(ull)(m0 + row) * NSPLITS + nblk] = b1;   // [token][split]
        g_top2[(ull)(m0 + row) * NSPLITS + nblk] = b2;
    }
}

// ---------------------------------------------------------------------------
// K2a: warp-per-token split merge + near-tie exact fp32 fixup (lane-parallel)
// ---------------------------------------------------------------------------
__global__ void k_assign(const float* __restrict__ z, const float* __restrict__ E,
                         float* __restrict__ out) {
    const int gtid = blockIdx.x * 256 + threadIdx.x;
    const int n    = gtid >> 5;          // token = warp
    const int lane = gtid & 31;
    if (n >= NTOK) return;

    const ull* t1p = g_top1 + (ull)n * NSPLITS;
    const ull* t2p = g_top2 + (ull)n * NSPLITS;
    // issue all four loads first (ILP), then merge
    ull t1a = t1p[lane],      t2a = t2p[lane];
    ull t1b = t1p[lane + 32], t2b = t2p[lane + 32];
    ull b1 = 0ull, b2 = 0ull;
    {
        if (t1a > b1)      { b2 = b1; b1 = t1a; }
        else if (t1a > b2) { b2 = t1a; }
        if (t2a > b2)      { b2 = t2a; }
        if (t1b > b1)      { b2 = b1; b1 = t1b; }
        else if (t1b > b2) { b2 = t1b; }
        if (t2b > b2)      { b2 = t2b; }
    }
    #pragma unroll
    for (int sh = 16; sh >= 1; sh >>= 1) {
        ull o1 = __shfl_xor_sync(0xffffffffu, b1, sh);
        ull o2 = __shfl_xor_sync(0xffffffffu, b2, sh);
        ull n1 = umax(b1, o1);
        ull n2 = umax(umin(b1, o1), umax(b2, o2));
        b1 = n1; b2 = n2;
    }

    int i1 = (KCODES - 1) - (int)(uint)(b1 & 0xffffffffu);
    int i2 = (KCODES - 1) - (int)(uint)(b2 & 0xffffffffu);
    uint m1 = ~(uint)(b1 >> 32), m2 = ~(uint)(b2 >> 32);
    float d1 = __uint_as_float((m1 & 0x80000000u) ? (m1 & 0x7fffffffu) : ~m1);
    float d2 = __uint_as_float((m2 & 0x80000000u) ? (m2 & 0x7fffffffu) : ~m2);

    int idx = i1;
    if (d2 - d1 < 2e-4f) {
        // exact fp32 re-score, lane-parallel (8 dims/lane), bucketed like ref
        int b = n >> 10, hw = n & 1023;
        const float* zp  = z + b * DD * HW + hw;
        const float* ep1 = E + i1;
        const float* ep2 = E + i2;
        float dot1 = 0.0f, dot2 = 0.0f;
        #pragma unroll
        for (int t = 0; t < 8; t++) {
            int d = t * 32 + lane;
            float zv = zp[d * HW];
            dot1 = fmaf(zv, ep1[d * KCODES], dot1);
            dot2 = fmaf(zv, ep2[d * KCODES], dot2);
        }
        #pragma unroll
        for (int sh = 16; sh >= 1; sh >>= 1) {
            dot1 += __shfl_xor_sync(0xffffffffu, dot1, sh);
            dot2 += __shfl_xor_sync(0xffffffffu, dot2, sh);
        }
        float sx2 = g_sx2[n];
        float e1  = (sx2 - 2.0f * dot1) + g_e2[i1];
        float e2x = (sx2 - 2.0f * dot2) + g_e2[i2];
        if (e2x < e1 || (e2x == e1 && i2 < i1)) idx = i2;
    }
    if (lane == 0) {
        g_idx[n] = idx;
        out[OUT_IDX + n] = (float)idx;
        atomicAdd(&out[OUT_CS + idx], 1.0f);
    }
}

// ---------------------------------------------------------------------------
// K2b: gather quantized (NCHW), scatter dw, accumulate loss. Vectorized:
// each thread handles 4 consecutive hw (float4 z read / Q write, int4 idx).
// grid (HW/128=8, DD/8=32, 8) = 2048 blocks, 256 threads.
// ---------------------------------------------------------------------------
__global__ void k_scatter(const float* __restrict__ z, const float* __restrict__ E,
                          float* __restrict__ out) {
    __shared__ float red[256];

    int tx  = threadIdx.x & 31;          // hw quad
    int ty  = threadIdx.x >> 5;          // d
    int hw4 = blockIdx.x * 128 + tx * 4;
    int d   = blockIdx.y * 8 + ty;
    int b   = blockIdx.z;

    int nb = b * HW + hw4;
    int4 idx4 = *(const int4*)&g_idx[nb];
    const float* Ed = E + (ull)d * KCODES;
    float q0 = Ed[idx4.x], q1 = Ed[idx4.y], q2 = Ed[idx4.z], q3 = Ed[idx4.w];

    int zi = (b * DD + d) * HW + hw4;
    float4 zv = *(const float4*)&z[zi];
    *(float4*)&out[OUT_Q + zi] = make_float4(q0, q1, q2, q3);

    float* dwd = out + OUT_DW + (ull)d * KCODES;
    atomicAdd(&dwd[idx4.x], zv.x);
    atomicAdd(&dwd[idx4.y], zv.y);
    atomicAdd(&dwd[idx4.z], zv.z);
    atomicAdd(&dwd[idx4.w], zv.w);

    float d0 = q0 - zv.x, d1 = q1 - zv.y, d2 = q2 - zv.z, d3 = q3 - zv.w;
    red[threadIdx.x] = d0 * d0 + d1 * d1 + d2 * d2 + d3 * d3;
    __syncthreads();
    #pragma unroll
    for (int s = 128; s > 0; s >>= 1) {
        if (threadIdx.x < s) red[threadIdx.x] += red[threadIdx.x + s];
        __syncthreads();
    }
    if (threadIdx.x == 0) atomicAdd(&g_loss, (double)red[0]);
}

// ---------------------------------------------------------------------------
// K3: loss + perplexity
// ---------------------------------------------------------------------------
__global__ void k_final(float* __restrict__ out) {
    __shared__ float red[256];
    int t = threadIdx.x;
    float s = 0.0f;
    for (int k = t; k < KCODES; k += 256) {
        float p = out[OUT_CS + k] * (1.0f / 8192.0f);
        s += p * logf(p + 1e-10f);
    }
    red[t] = s;
    __syncthreads();
    #pragma unroll
    for (int st = 128; st > 0; st >>= 1) {
        if (t < st) red[t] += red[t + st];
        __syncthreads();
    }
    if (t == 0) {
        out[OUT_PERP] = expf(-red[0]);
        out[OUT_LOSS] = (float)(0.25 * g_loss / 2097152.0);
    }
}

// ---------------------------------------------------------------------------
extern "C" void kernel_launch(void* const* d_in, const int* in_sizes, int n_in,
                              void* d_out, int out_size) {
    const float* z = (const float*)d_in[0];         // [8,256,32,32]
    const float* E = (const float*)d_in[1];         // [256,8192]
    float* out = (float*)d_out;

    cudaFuncSetAttribute(k_mma, cudaFuncAttributeMaxDynamicSharedMemorySize,
                         SMEM_DYN);

    k_prep   <<< 512, 256 >>>(z, E, out);
    k_mma    <<< dim3(NTOK / MTILE, NSPLITS), 128, SMEM_DYN >>>();
    k_assign <<< (NTOK * 32) / 256, 256 >>>(z, E, out);
    k_scatter<<< dim3(HW / 128, DD / 8, BATCH), 256 >>>(z, E, out);
    k_final  <<< 1, 256 >>>(out);
}

// round 15
// speedup vs baseline: 1.4489x; 1.3109x over previous
#include <cuda_runtime.h>
#include <cuda_fp16.h>
#include <math.h>

// Problem constants
#define DD      256
#define KCODES  8192
#define BATCH   8
#define HW      1024
#define NTOK    8192

// Output layout (flattened return tuple, in order)
#define OUT_Q     0
#define OUT_LOSS  2097152
#define OUT_PERP  2097153
#define OUT_IDX   2097154
#define OUT_DW    2105346
#define OUT_CS    4202498

// GEMM config: C[8192 tok, 8192 codes] = A[.,512] * B[.,512]^T  (fp16 2-term)
//   A row = [xh | xh],  B row = [eh | el]  =>  dot = xh*(eh+el) ~= x*e
#define KTOT    512
#define MTILE   128
#define NTILE   128
#define KS      64
#define NSTAGES 8                     // 512/64
#define NPIPE   3                     // cp.async pipeline depth
#define NSPLITS (KCODES / NTILE)      // 64
#define ABYTES  16384                 // per-stage A buffer (128 x 128B)
#define BBYTES  16384                 // per-stage B buffer
#define SM_RED  (NPIPE * (ABYTES + BBYTES))    // 98304: sred after tiles
#define SMEM_DYN (SM_RED + 4096)               // 100KB/CTA -> 2 CTAs/SM

#define PREP_PAD 257                  // stride mod 32 == 1 -> conflict-free

typedef unsigned long long ull;
typedef unsigned int uint;

// ---------------- device scratch (no allocation allowed) --------------------
__device__ __half g_A[NTOK   * KTOT];  // [tok ][xh(256)|xh(256)] fp16
__device__ __half g_B[KCODES * KTOT];  // [code][eh(256)|el(256)] fp16
__device__ float  g_e2[KCODES];
__device__ float  g_sx2[NTOK];
__device__ ull    g_top1[NTOK * NSPLITS];     // [token][split]  (coalesced merge)
__device__ ull    g_top2[NTOK * NSPLITS];
__device__ int    g_idx[NTOK];
__device__ double g_loss;

// ---------------- PTX helpers (all plain-sm_100 legal) ----------------------
__device__ __forceinline__ uint smem_u32(const void* p) {
    uint a;
    asm("{ .reg .u64 t; cvta.to.shared.u64 t, %1; cvt.u32.u64 %0, t; }"
        : "=r"(a) : "l"(p));
    return a;
}
#define CP16(dst, src) \
    asm volatile("cp.async.cg.shared.global [%0], [%1], 16;" :: "r"(dst), "l"(src))
#define CP_COMMIT() asm volatile("cp.async.commit_group;")
#define CP_WAIT(n)  asm volatile("cp.async.wait_group %0;" :: "n"(n))

#define LDSM4(r0, r1, r2, r3, a) \
    asm volatile("ldmatrix.sync.aligned.m8n8.x4.shared.b16 {%0,%1,%2,%3}, [%4];" \
        : "=r"(r0), "=r"(r1), "=r"(r2), "=r"(r3) : "r"(a))

#define MMA16816(c, a, b) \
    asm volatile("mma.sync.aligned.m16n8k16.row.col.f32.f16.f16.f32 " \
        "{%0,%1,%2,%3}, {%4,%5,%6,%7}, {%8,%9}, {%0,%1,%2,%3};" \
        : "+f"((c)[0]), "+f"((c)[1]), "+f"((c)[2]), "+f"((c)[3]) \
        : "r"((a)[0]), "r"((a)[1]), "r"((a)[2]), "r"((a)[3]), \
          "r"((b)[0]), "r"((b)[1]))

__device__ __forceinline__ ull umax(ull a, ull b) { return a > b ? a : b; }
__device__ __forceinline__ ull umin(ull a, ull b) { return a < b ? a : b; }

// ---------------------------------------------------------------------------
// K_prep (fused init + norms + transpose/split). Conflict-free smem (pad 257,
// split row = tid&31).
//   Blocks 0..255:   z -> g_A (32 tokens each) + g_sx2
//   Blocks 256..511: E -> g_B (32 codes each)  + g_e2
// ---------------------------------------------------------------------------
__global__ void k_prep(const float* __restrict__ z, const float* __restrict__ E,
                       float* __restrict__ out) {
    __shared__ float st[32 * PREP_PAD];
    const int tid = threadIdx.x;
    const bool isB = blockIdx.x >= 256;
    const int n0 = (isB ? (blockIdx.x - 256) : blockIdx.x) * 32;

    // zero dw + cluster_size (2105344 floats = 1052672 float2, 8B-aligned)
    {
        const float2 z2 = make_float2(0.0f, 0.0f);
        float2* dst2 = (float2*)(out + OUT_DW);
        for (int i = blockIdx.x * 256 + tid; i < 1052672; i += 512 * 256)
            dst2[i] = z2;
        if (blockIdx.x == 0 && tid == 0) g_loss = 0.0;
    }

    // load 32 rows x 256 dims into smem (transposed); stride 257 -> no conflicts
    for (int i = tid; i < 32 * 256; i += 256) {
        int k = i >> 5, nl = i & 31;
        float v;
        if (isB) v = E[k * KCODES + n0 + nl];
        else {
            int b = n0 >> 10, hw0 = n0 & 1023;
            v = z[(b * DD + k) * HW + hw0 + nl];
        }
        st[nl * PREP_PAD + k] = v;
    }
    __syncthreads();

    // norms: one thread per row, sequential fp32 over d (bit-identical path)
    if (tid < 32) {
        float s = 0.0f;
        #pragma unroll 8
        for (int d = 0; d < DD; d++) { float v = st[tid * PREP_PAD + d]; s += v * v; }
        if (isB) g_e2[n0 + tid] = s;
        else     g_sx2[n0 + tid] = s;
    }

    // fp16 split, packed stores:  A row [xh|xh],  B row [eh|el]
    __half* dst = isB ? g_B : g_A;
    const int nl = tid & 31;
    const int jb = (tid >> 5) * 32;
    __half* rowp = dst + (ull)(n0 + nl) * KTOT;

    uint hwv[16], lwv[16];
    #pragma unroll
    for (int t = 0; t < 16; t++) {
        float v0 = st[nl * PREP_PAD + jb + 2 * t];
        float v1 = st[nl * PREP_PAD + jb + 2 * t + 1];
        __half h0 = __float2half_rn(v0);
        __half h1 = __float2half_rn(v1);
        __half l0 = __float2half_rn(v0 - __half2float(h0));
        __half l1 = __float2half_rn(v1 - __half2float(h1));
        hwv[t] = (uint)__half_as_ushort(h0) | ((uint)__half_as_ushort(h1) << 16);
        lwv[t] = (uint)__half_as_ushort(l0) | ((uint)__half_as_ushort(l1) << 16);
    }
    uint4* p0 = (uint4*)(rowp + jb);            // hi
    uint4* p1 = (uint4*)(rowp + 256 + jb);      // B: lo,  A: hi (duplicate)
    #pragma unroll
    for (int t = 0; t < 4; t++) {
        uint4 hv = make_uint4(hwv[4*t], hwv[4*t+1], hwv[4*t+2], hwv[4*t+3]);
        uint4 lv = make_uint4(lwv[4*t], lwv[4*t+1], lwv[4*t+2], lwv[4*t+3]);
        p0[t] = hv;
        p1[t] = isB ? lv : hv;
    }
}

// ---------------------------------------------------------------------------
// K1: HMMA fp16 distance GEMM fused with per-token top-2 (R9 structure).
// CTA tile 128x128, 4 warps (2m x 2n), warp tile 64x64, NPIPE=3,
// 100KB smem -> 2 CTAs/SM. Grid (64 m-tiles, 64 n-blocks). K=512, 8 stages.
// ---------------------------------------------------------------------------
__global__ void __launch_bounds__(128, 2)
k_mma() {
    extern __shared__ char smem[];
    const uint sb  = smem_u32(smem);
    const uint sA  = sb;                       // 3 x 16KB
    const uint sB  = sb + NPIPE * ABYTES;      // 3 x 16KB
    ull* sred = (ull*)(smem + SM_RED);         // 4KB, separate from tiles

    const int tid  = threadIdx.x;
    const int lane = tid & 31;
    const int wid  = tid >> 5;      // 0..3
    const int wm   = wid & 1;       // m warp (2): 64 rows each
    const int wn   = wid >> 1;      // n warp (2): 64 cols each

    const int m0   = blockIdx.x * MTILE;
    const int nblk = blockIdx.y;
    const int n0   = nblk * NTILE;

    const __half* gA = g_A + (ull)m0 * KTOT;
    const __half* gB = g_B + (ull)n0 * KTOT;

    float c[4][8][4];
    #pragma unroll
    for (int i = 0; i < 4; i++)
        #pragma unroll
        for (int j = 0; j < 8; j++)
            #pragma unroll
            for (int r = 0; r < 4; r++) c[i][j][r] = 0.0f;

    // --- hoisted issue-side address components (tid-constant) ---
    const int ld_row = tid >> 3;           // 0..15
    const int ld_ch  = tid & 7;
    const uint ld_sw = (uint)((ld_ch ^ (ld_row & 7)) << 4);
    const uint dst_base = (uint)ld_row * 128u + ld_sw;
    const __half* srcA0 = gA + (ull)ld_row * KTOT + ld_ch * 8;
    const __half* srcB0 = gB + (ull)ld_row * KTOT + ld_ch * 8;

    // --- hoisted ldmatrix address components ---
    const int rowA = wm * 64 + (lane & 7) + ((lane >> 3) & 1) * 8;  // + i*16
    const int chA  = (lane >> 4);
    const int rowB = wn * 64 + (lane & 7) + ((lane >> 4) << 3);     // + nb*16
    const int chB  = (lane >> 3) & 1;
    uint colA[4], colB[4];
    #pragma unroll
    for (int ks = 0; ks < 4; ks++) {
        colA[ks] = (uint)(((ks * 2 + chA) ^ (rowA & 7)) << 4);
        colB[ks] = (uint)(((ks * 2 + chB) ^ (rowB & 7)) << 4);
    }
    uint rbaseA[4], rbaseB[4];
    #pragma unroll
    for (int i = 0; i < 4; i++) rbaseA[i] = (uint)(rowA + i * 16) * 128u;
    #pragma unroll
    for (int i = 0; i < 4; i++) rbaseB[i] = (uint)(rowB + i * 16) * 128u;

    // stage issuer: 8 A-chunks + 8 B-chunks of 16B per thread (128 threads)
    auto issue = [&](int s, int buf) {
        const int kb = s * KS;
        const uint bufA = sA + (uint)buf * ABYTES;
        const uint bufB = sB + (uint)buf * BBYTES;
        const __half* sa  = srcA0 + kb;
        const __half* sbp = srcB0 + kb;
        #pragma unroll
        for (int i = 0; i < 8; i++)
            CP16(bufA + dst_base + (uint)i * 2048u, sa + (ull)i * 16 * KTOT);
        #pragma unroll
        for (int i = 0; i < 8; i++)
            CP16(bufB + dst_base + (uint)i * 2048u, sbp + (ull)i * 16 * KTOT);
        CP_COMMIT();
    };

    issue(0, 0); issue(1, 1);

    int buf = 0;
    for (int s = 0; s < NSTAGES; s++) {
        if (s < NSTAGES - 1) { CP_WAIT(1); } else { CP_WAIT(0); }
        __syncthreads();

        const uint bufA = sA + (uint)buf * ABYTES;
        const uint bufB = sB + (uint)buf * BBYTES;

        #pragma unroll
        for (int ks = 0; ks < 4; ks++) {
            uint a[4][4];
            #pragma unroll
            for (int i = 0; i < 4; i++)
                LDSM4(a[i][0], a[i][1], a[i][2], a[i][3],
                      bufA + rbaseA[i] + colA[ks]);
            uint b[8][2];
            #pragma unroll
            for (int nb = 0; nb < 4; nb++) {
                uint r0, r1, r2, r3;
                LDSM4(r0, r1, r2, r3, bufB + rbaseB[nb] + colB[ks]);
                b[nb * 2][0] = r0;     b[nb * 2][1] = r1;
                b[nb * 2 + 1][0] = r2; b[nb * 2 + 1][1] = r3;
            }
            #pragma unroll
            for (int i = 0; i < 4; i++)
                #pragma unroll
                for (int j = 0; j < 8; j++)
                    MMA16816(c[i][j], a[i], b[j]);
        }
        if (s + 2 < NSTAGES) {
            int nbuf = buf + 2; if (nbuf >= NPIPE) nbuf -= NPIPE;
            issue(s + 2, nbuf);
        }
        if (++buf == NPIPE) buf = 0;
    }

    // ---------------- epilogue: dist + top-2, no atomics --------------------
    float e2v[8][2];
    #pragma unroll
    for (int j = 0; j < 8; j++)
        #pragma unroll
        for (int q = 0; q < 2; q++)
            e2v[j][q] = g_e2[n0 + wn * 64 + j * 8 + (lane & 3) * 2 + q];

    #pragma unroll
    for (int i = 0; i < 4; i++) {
        #pragma unroll
        for (int h = 0; h < 2; h++) {
            const int m_local = wm * 64 + i * 16 + (lane >> 2) + h * 8;
            const float sx2 = g_sx2[m0 + m_local];
            ull b1 = 0ull, b2 = 0ull;
            #pragma unroll
            for (int j = 0; j < 8; j++) {
                #pragma unroll
                for (int q = 0; q < 2; q++) {
                    float dot  = c[i][j][h * 2 + q];
                    float dist = (sx2 - 2.0f * dot) + e2v[j][q];
                    const int n = n0 + wn * 64 + j * 8 + (lane & 3) * 2 + q;
                    uint u = __float_as_uint(dist);
                    uint m = (u & 0x80000000u) ? ~u : (u | 0x80000000u);
                    ull key = ((ull)(~m) << 32) | (uint)(KCODES - 1 - n);
                    if (key > b1)      { b2 = b1; b1 = key; }
                    else if (key > b2) { b2 = key; }
                }
            }
            #pragma unroll
            for (int sh = 1; sh <= 2; sh <<= 1) {
                ull o1 = __shfl_xor_sync(0xffffffffu, b1, sh);
                ull o2 = __shfl_xor_sync(0xffffffffu, b2, sh);
                ull n1 = umax(b1, o1);
                ull n2 = umax(umin(b1, o1), umax(b2, o2));
                b1 = n1; b2 = n2;
            }
            if ((lane & 3) == 0) {
                sred[(m_local * 2 + wn) * 2 + 0] = b1;
                sred[(m_local * 2 + wn) * 2 + 1] = b2;
            }
        }
    }
    __syncthreads();
    {
        const int row = tid;   // 128 rows, 128 threads
        ull p1a = sred[(row * 2 + 0) * 2 + 0], p2a = sred[(row * 2 + 0) * 2 + 1];
        ull p1b = sred[(row * 2 + 1) * 2 + 0], p2b = sred[(row * 2 + 1) * 2 + 1];
        ull b1 = umax(p1a, p1b);
        ull b2 = umax(umin(p1a, p1b), umax(p2a, p2b));
        g_top1[(ull)(m0 + row) * NSPLITS + nblk] = b1;   // [token][split]
        g_top2[(ull)(m0 + row) * NSPLITS + nblk] = b2;
    }
}

// ---------------------------------------------------------------------------
// K2a: warp-per-token split merge + near-tie exact fp32 fixup (lane-parallel)
// ---------------------------------------------------------------------------
__global__ void k_assign(const float* __restrict__ z, const float* __restrict__ E,
                         float* __restrict__ out) {
    const int gtid = blockIdx.x * 256 + threadIdx.x;
    const int n    = gtid >> 5;          // token = warp
    const int lane = gtid & 31;
    if (n >= NTOK) return;

    const ull* t1p = g_top1 + (ull)n * NSPLITS;
    const ull* t2p = g_top2 + (ull)n * NSPLITS;
    ull t1a = t1p[lane],      t2a = t2p[lane];
    ull t1b = t1p[lane + 32], t2b = t2p[lane + 32];
    ull b1 = 0ull, b2 = 0ull;
    {
        if (t1a > b1)      { b2 = b1; b1 = t1a; }
        else if (t1a > b2) { b2 = t1a; }
        if (t2a > b2)      { b2 = t2a; }
        if (t1b > b1)      { b2 = b1; b1 = t1b; }
        else if (t1b > b2) { b2 = t1b; }
        if (t2b > b2)      { b2 = t2b; }
    }
    #pragma unroll
    for (int sh = 16; sh >= 1; sh >>= 1) {
        ull o1 = __shfl_xor_sync(0xffffffffu, b1, sh);
        ull o2 = __shfl_xor_sync(0xffffffffu, b2, sh);
        ull n1 = umax(b1, o1);
        ull n2 = umax(umin(b1, o1), umax(b2, o2));
        b1 = n1; b2 = n2;
    }

    int i1 = (KCODES - 1) - (int)(uint)(b1 & 0xffffffffu);
    int i2 = (KCODES - 1) - (int)(uint)(b2 & 0xffffffffu);
    uint m1 = ~(uint)(b1 >> 32), m2 = ~(uint)(b2 >> 32);
    float d1 = __uint_as_float((m1 & 0x80000000u) ? (m1 & 0x7fffffffu) : ~m1);
    float d2 = __uint_as_float((m2 & 0x80000000u) ? (m2 & 0x7fffffffu) : ~m2);

    int idx = i1;
    if (d2 - d1 < 5e-4f) {
        // exact fp32 re-score, lane-parallel (8 dims/lane), bucketed like ref
        int b = n >> 10, hw = n & 1023;
        const float* zp  = z + b * DD * HW + hw;
        const float* ep1 = E + i1;
        const float* ep2 = E + i2;
        float dot1 = 0.0f, dot2 = 0.0f;
        #pragma unroll
        for (int t = 0; t < 8; t++) {
            int d = t * 32 + lane;
            float zv = zp[d * HW];
            dot1 = fmaf(zv, ep1[d * KCODES], dot1);
            dot2 = fmaf(zv, ep2[d * KCODES], dot2);
        }
        #pragma unroll
        for (int sh = 16; sh >= 1; sh >>= 1) {
            dot1 += __shfl_xor_sync(0xffffffffu, dot1, sh);
            dot2 += __shfl_xor_sync(0xffffffffu, dot2, sh);
        }
        float sx2 = g_sx2[n];
        float e1  = (sx2 - 2.0f * dot1) + g_e2[i1];
        float e2x = (sx2 - 2.0f * dot2) + g_e2[i2];
        if (e2x < e1 || (e2x == e1 && i2 < i1)) idx = i2;
    }
    if (lane == 0) {
        g_idx[n] = idx;
        out[OUT_IDX + n] = (float)idx;
        atomicAdd(&out[OUT_CS + idx], 1.0f);
    }
}

// ---------------------------------------------------------------------------
// K2b: gather quantized (NCHW), scatter dw, accumulate loss (vectorized x4)
// ---------------------------------------------------------------------------
__global__ void k_scatter(const float* __restrict__ z, const float* __restrict__ E,
                          float* __restrict__ out) {
    __shared__ float red[256];

    int tx  = threadIdx.x & 31;          // hw quad
    int ty  = threadIdx.x >> 5;          // d
    int hw4 = blockIdx.x * 128 + tx * 4;
    int d   = blockIdx.y * 8 + ty;
    int b   = blockIdx.z;

    int nb = b * HW + hw4;
    int4 idx4 = *(const int4*)&g_idx[nb];
    const float* Ed = E + (ull)d * KCODES;
    float q0 = Ed[idx4.x], q1 = Ed[idx4.y], q2 = Ed[idx4.z], q3 = Ed[idx4.w];

    int zi = (b * DD + d) * HW + hw4;
    float4 zv = *(const float4*)&z[zi];
    *(float4*)&out[OUT_Q + zi] = make_float4(q0, q1, q2, q3);

    float* dwd = out + OUT_DW + (ull)d * KCODES;
    atomicAdd(&dwd[idx4.x], zv.x);
    atomicAdd(&dwd[idx4.y], zv.y);
    atomicAdd(&dwd[idx4.z], zv.z);
    atomicAdd(&dwd[idx4.w], zv.w);

    float d0 = q0 - zv.x, d1 = q1 - zv.y, d2 = q2 - zv.z, d3 = q3 - zv.w;
    red[threadIdx.x] = d0 * d0 + d1 * d1 + d2 * d2 + d3 * d3;
    __syncthreads();
    #pragma unroll
    for (int s = 128; s > 0; s >>= 1) {
        if (threadIdx.x < s) red[threadIdx.x] += red[threadIdx.x + s];
        __syncthreads();
    }
    if (threadIdx.x == 0) atomicAdd(&g_loss, (double)red[0]);
}

// ---------------------------------------------------------------------------
// K3: loss + perplexity
// ---------------------------------------------------------------------------
__global__ void k_final(float* __restrict__ out) {
    __shared__ float red[256];
    int t = threadIdx.x;
    float s = 0.0f;
    for (int k = t; k < KCODES; k += 256) {
        float p = out[OUT_CS + k] * (1.0f / 8192.0f);
        s += p * logf(p + 1e-10f);
    }
    red[t] = s;
    __syncthreads();
    #pragma unroll
    for (int st = 128; st > 0; st >>= 1) {
        if (t < st) red[t] += red[t + st];
        __syncthreads();
    }
    if (t == 0) {
        out[OUT_PERP] = expf(-red[0]);
        out[OUT_LOSS] = (float)(0.25 * g_loss / 2097152.0);
    }
}

// ---------------------------------------------------------------------------
extern "C" void kernel_launch(void* const* d_in, const int* in_sizes, int n_in,
                              void* d_out, int out_size) {
    const float* z = (const float*)d_in[0];         // [8,256,32,32]
    const float* E = (const float*)d_in[1];         // [256,8192]
    float* out = (float*)d_out;

    cudaFuncSetAttribute(k_mma, cudaFuncAttributeMaxDynamicSharedMemorySize,
                         SMEM_DYN);

    k_prep   <<< 512, 256 >>>(z, E, out);
    k_mma    <<< dim3(NTOK / MTILE, NSPLITS), 128, SMEM_DYN >>>();
    k_assign <<< (NTOK * 32) / 256, 256 >>>(z, E, out);
    k_scatter<<< dim3(HW / 128, DD / 8, BATCH), 256 >>>(z, E, out);
    k_final  <<< 1, 256 >>>(out);
}

// round 16
// speedup vs baseline: 1.6744x; 1.1557x over previous
#include <cuda_runtime.h>
#include <cuda_fp16.h>
#include <math.h>

// Problem constants
#define DD      256
#define KCODES  8192
#define BATCH   8
#define HW      1024
#define NTOK    8192

// Output layout (flattened return tuple, in order)
#define OUT_Q     0
#define OUT_LOSS  2097152
#define OUT_PERP  2097153
#define OUT_IDX   2097154
#define OUT_DW    2105346
#define OUT_CS    4202498

// GEMM config: C[8192 tok, 8192 codes] = A[.,256] * B[.,256]^T  (fp16 1-term)
//   A row = [xh],  B row = [eh]  =>  dot = xh*eh ~= x*e  (guarded by top-3)
#define KTOT    256
#define MTILE   128
#define NTILE   128
#define KS      64
#define NSTAGES 4                     // 256/64
#define NPIPE   3                     // cp.async pipeline depth
#define NSPLITS (KCODES / NTILE)      // 64
#define ABYTES  16384                 // per-stage A buffer (128 x 128B)
#define BBYTES  16384                 // per-stage B buffer
#define SM_RED  (NPIPE * (ABYTES + BBYTES))    // 98304: sred after tiles
#define SMEM_DYN (SM_RED + 8192)               // +6KB top-3 scratch -> 104KB

#define PREP_PAD 257                  // stride mod 32 == 1 -> conflict-free

typedef unsigned long long ull;
typedef unsigned int uint;

// ---------------- device scratch (no allocation allowed) --------------------
__device__ __half g_A[NTOK   * KTOT];  // [tok ][xh(256)] fp16
__device__ __half g_B[KCODES * KTOT];  // [code][eh(256)] fp16
__device__ float  g_e2[KCODES];
__device__ float  g_sx2[NTOK];
__device__ ull    g_top1[NTOK * NSPLITS];     // [token][split]
__device__ ull    g_top2[NTOK * NSPLITS];
__device__ ull    g_top3[NTOK * NSPLITS];
__device__ int    g_idx[NTOK];
__device__ double g_loss;

// ---------------- PTX helpers (all plain-sm_100 legal) ----------------------
__device__ __forceinline__ uint smem_u32(const void* p) {
    uint a;
    asm("{ .reg .u64 t; cvta.to.shared.u64 t, %1; cvt.u32.u64 %0, t; }"
        : "=r"(a) : "l"(p));
    return a;
}
#define CP16(dst, src) \
    asm volatile("cp.async.cg.shared.global [%0], [%1], 16;" :: "r"(dst), "l"(src))
#define CP_COMMIT() asm volatile("cp.async.commit_group;")
#define CP_WAIT(n)  asm volatile("cp.async.wait_group %0;" :: "n"(n))

#define LDSM4(r0, r1, r2, r3, a) \
    asm volatile("ldmatrix.sync.aligned.m8n8.x4.shared.b16 {%0,%1,%2,%3}, [%4];" \
        : "=r"(r0), "=r"(r1), "=r"(r2), "=r"(r3) : "r"(a))

#define MMA16816(c, a, b) \
    asm volatile("mma.sync.aligned.m16n8k16.row.col.f32.f16.f16.f32 " \
        "{%0,%1,%2,%3}, {%4,%5,%6,%7}, {%8,%9}, {%0,%1,%2,%3};" \
        : "+f"((c)[0]), "+f"((c)[1]), "+f"((c)[2]), "+f"((c)[3]) \
        : "r"((a)[0]), "r"((a)[1]), "r"((a)[2]), "r"((a)[3]), \
          "r"((b)[0]), "r"((b)[1]))

__device__ __forceinline__ ull umax(ull a, ull b) { return a > b ? a : b; }
__device__ __forceinline__ ull umin(ull a, ull b) { return a < b ? a : b; }

// merge two sorted-descending triples -> top-3 of union
__device__ __forceinline__ void merge3(ull& a1, ull& a2, ull& a3,
                                       ull o1, ull o2, ull o3) {
    ull c1 = umax(a1, o1);
    ull p  = umin(a1, o1);
    ull q  = umax(a2, o2);
    ull r  = umin(a2, o2);
    ull s  = umax(a3, o3);
    ull c2 = umax(p, q);
    ull c3 = umax(umin(p, q), umax(r, s));
    a1 = c1; a2 = c2; a3 = c3;
}

// ---------------------------------------------------------------------------
// K_prep (fused init + norms + fp16 transpose). Conflict-free smem.
//   Blocks 0..255:   z -> g_A (32 tokens each) + g_sx2
//   Blocks 256..511: E -> g_B (32 codes each)  + g_e2
// ---------------------------------------------------------------------------
__global__ void k_prep(const float* __restrict__ z, const float* __restrict__ E,
                       float* __restrict__ out) {
    __shared__ float st[32 * PREP_PAD];
    const int tid = threadIdx.x;
    const bool isB = blockIdx.x >= 256;
    const int n0 = (isB ? (blockIdx.x - 256) : blockIdx.x) * 32;

    // zero dw + cluster_size (2105344 floats = 1052672 float2, 8B-aligned)
    {
        const float2 z2 = make_float2(0.0f, 0.0f);
        float2* dst2 = (float2*)(out + OUT_DW);
        for (int i = blockIdx.x * 256 + tid; i < 1052672; i += 512 * 256)
            dst2[i] = z2;
        if (blockIdx.x == 0 && tid == 0) g_loss = 0.0;
    }

    // load 32 rows x 256 dims into smem (transposed); stride 257 -> no conflicts
    for (int i = tid; i < 32 * 256; i += 256) {
        int k = i >> 5, nl = i & 31;
        float v;
        if (isB) v = E[k * KCODES + n0 + nl];
        else {
            int b = n0 >> 10, hw0 = n0 & 1023;
            v = z[(b * DD + k) * HW + hw0 + nl];
        }
        st[nl * PREP_PAD + k] = v;
    }
    __syncthreads();

    // norms: one thread per row, sequential fp32 over d (bit-identical path)
    if (tid < 32) {
        float s = 0.0f;
        #pragma unroll 8
        for (int d = 0; d < DD; d++) { float v = st[tid * PREP_PAD + d]; s += v * v; }
        if (isB) g_e2[n0 + tid] = s;
        else     g_sx2[n0 + tid] = s;
    }

    // fp16 convert, packed stores: single hi term
    __half* dst = isB ? g_B : g_A;
    const int nl = tid & 31;
    const int jb = (tid >> 5) * 32;
    __half* rowp = dst + (ull)(n0 + nl) * KTOT;

    uint hwv[16];
    #pragma unroll
    for (int t = 0; t < 16; t++) {
        float v0 = st[nl * PREP_PAD + jb + 2 * t];
        float v1 = st[nl * PREP_PAD + jb + 2 * t + 1];
        __half h0 = __float2half_rn(v0);
        __half h1 = __float2half_rn(v1);
        hwv[t] = (uint)__half_as_ushort(h0) | ((uint)__half_as_ushort(h1) << 16);
    }
    uint4* p0 = (uint4*)(rowp + jb);
    #pragma unroll
    for (int t = 0; t < 4; t++)
        p0[t] = make_uint4(hwv[4*t], hwv[4*t+1], hwv[4*t+2], hwv[4*t+3]);
}

// ---------------------------------------------------------------------------
// K1: HMMA fp16 distance GEMM fused with per-token top-3.
// CTA tile 128x128, 4 warps (2m x 2n), warp tile 64x64, NPIPE=3, K=256
// (4 stages), 104KB smem -> 2 CTAs/SM. Grid (64 m-tiles, 64 n-blocks).
// ---------------------------------------------------------------------------
__global__ void __launch_bounds__(128, 2)
k_mma() {
    extern __shared__ char smem[];
    const uint sb  = smem_u32(smem);
    const uint sA  = sb;                       // 3 x 16KB
    const uint sB  = sb + NPIPE * ABYTES;      // 3 x 16KB
    ull* sred = (ull*)(smem + SM_RED);         // 6KB: [128][2][3]

    const int tid  = threadIdx.x;
    const int lane = tid & 31;
    const int wid  = tid >> 5;      // 0..3
    const int wm   = wid & 1;       // m warp (2): 64 rows each
    const int wn   = wid >> 1;      // n warp (2): 64 cols each

    const int m0   = blockIdx.x * MTILE;
    const int nblk = blockIdx.y;
    const int n0   = nblk * NTILE;

    const __half* gA = g_A + (ull)m0 * KTOT;
    const __half* gB = g_B + (ull)n0 * KTOT;

    float c[4][8][4];
    #pragma unroll
    for (int i = 0; i < 4; i++)
        #pragma unroll
        for (int j = 0; j < 8; j++)
            #pragma unroll
            for (int r = 0; r < 4; r++) c[i][j][r] = 0.0f;

    // --- hoisted issue-side address components (tid-constant) ---
    const int ld_row = tid >> 3;           // 0..15
    const int ld_ch  = tid & 7;
    const uint ld_sw = (uint)((ld_ch ^ (ld_row & 7)) << 4);
    const uint dst_base = (uint)ld_row * 128u + ld_sw;
    const __half* srcA0 = gA + (ull)ld_row * KTOT + ld_ch * 8;
    const __half* srcB0 = gB + (ull)ld_row * KTOT + ld_ch * 8;

    // --- hoisted ldmatrix address components ---
    const int rowA = wm * 64 + (lane & 7) + ((lane >> 3) & 1) * 8;  // + i*16
    const int chA  = (lane >> 4);
    const int rowB = wn * 64 + (lane & 7) + ((lane >> 4) << 3);     // + nb*16
    const int chB  = (lane >> 3) & 1;
    uint colA[4], colB[4];
    #pragma unroll
    for (int ks = 0; ks < 4; ks++) {
        colA[ks] = (uint)(((ks * 2 + chA) ^ (rowA & 7)) << 4);
        colB[ks] = (uint)(((ks * 2 + chB) ^ (rowB & 7)) << 4);
    }
    uint rbaseA[4], rbaseB[4];
    #pragma unroll
    for (int i = 0; i < 4; i++) rbaseA[i] = (uint)(rowA + i * 16) * 128u;
    #pragma unroll
    for (int i = 0; i < 4; i++) rbaseB[i] = (uint)(rowB + i * 16) * 128u;

    // stage issuer: 8 A-chunks + 8 B-chunks of 16B per thread (128 threads)
    auto issue = [&](int s, int buf) {
        const int kb = s * KS;
        const uint bufA = sA + (uint)buf * ABYTES;
        const uint bufB = sB + (uint)buf * BBYTES;
        const __half* sa  = srcA0 + kb;
        const __half* sbp = srcB0 + kb;
        #pragma unroll
        for (int i = 0; i < 8; i++)
            CP16(bufA + dst_base + (uint)i * 2048u, sa + (ull)i * 16 * KTOT);
        #pragma unroll
        for (int i = 0; i < 8; i++)
            CP16(bufB + dst_base + (uint)i * 2048u, sbp + (ull)i * 16 * KTOT);
        CP_COMMIT();
    };

    issue(0, 0); issue(1, 1);

    int buf = 0;
    for (int s = 0; s < NSTAGES; s++) {
        if (s < NSTAGES - 1) { CP_WAIT(1); } else { CP_WAIT(0); }
        __syncthreads();

        const uint bufA = sA + (uint)buf * ABYTES;
        const uint bufB = sB + (uint)buf * BBYTES;

        #pragma unroll
        for (int ks = 0; ks < 4; ks++) {
            uint a[4][4];
            #pragma unroll
            for (int i = 0; i < 4; i++)
                LDSM4(a[i][0], a[i][1], a[i][2], a[i][3],
                      bufA + rbaseA[i] + colA[ks]);
            uint b[8][2];
            #pragma unroll
            for (int nb = 0; nb < 4; nb++) {
                uint r0, r1, r2, r3;
                LDSM4(r0, r1, r2, r3, bufB + rbaseB[nb] + colB[ks]);
                b[nb * 2][0] = r0;     b[nb * 2][1] = r1;
                b[nb * 2 + 1][0] = r2; b[nb * 2 + 1][1] = r3;
            }
            #pragma unroll
            for (int i = 0; i < 4; i++)
                #pragma unroll
                for (int j = 0; j < 8; j++)
                    MMA16816(c[i][j], a[i], b[j]);
        }
        if (s + 2 < NSTAGES) {
            int nbuf = buf + 2; if (nbuf >= NPIPE) nbuf -= NPIPE;
            issue(s + 2, nbuf);
        }
        if (++buf == NPIPE) buf = 0;
    }

    // ---------------- epilogue: dist + top-3, no atomics --------------------
    float e2v[8][2];
    #pragma unroll
    for (int j = 0; j < 8; j++)
        #pragma unroll
        for (int q = 0; q < 2; q++)
            e2v[j][q] = g_e2[n0 + wn * 64 + j * 8 + (lane & 3) * 2 + q];

    #pragma unroll
    for (int i = 0; i < 4; i++) {
        #pragma unroll
        for (int h = 0; h < 2; h++) {
            const int m_local = wm * 64 + i * 16 + (lane >> 2) + h * 8;
            const float sx2 = g_sx2[m0 + m_local];
            ull b1 = 0ull, b2 = 0ull, b3 = 0ull;
            #pragma unroll
            for (int j = 0; j < 8; j++) {
                #pragma unroll
                for (int q = 0; q < 2; q++) {
                    float dot  = c[i][j][h * 2 + q];
                    float dist = (sx2 - 2.0f * dot) + e2v[j][q];
                    const int n = n0 + wn * 64 + j * 8 + (lane & 3) * 2 + q;
                    uint u = __float_as_uint(dist);
                    uint m = (u & 0x80000000u) ? ~u : (u | 0x80000000u);
                    ull key = ((ull)(~m) << 32) | (uint)(KCODES - 1 - n);
                    if (key > b1)      { b3 = b2; b2 = b1; b1 = key; }
                    else if (key > b2) { b3 = b2; b2 = key; }
                    else if (key > b3) { b3 = key; }
                }
            }
            #pragma unroll
            for (int sh = 1; sh <= 2; sh <<= 1) {
                ull o1 = __shfl_xor_sync(0xffffffffu, b1, sh);
                ull o2 = __shfl_xor_sync(0xffffffffu, b2, sh);
                ull o3 = __shfl_xor_sync(0xffffffffu, b3, sh);
                merge3(b1, b2, b3, o1, o2, o3);
            }
            if ((lane & 3) == 0) {
                sred[(m_local * 2 + wn) * 3 + 0] = b1;
                sred[(m_local * 2 + wn) * 3 + 1] = b2;
                sred[(m_local * 2 + wn) * 3 + 2] = b3;
            }
        }
    }
    __syncthreads();
    {
        const int row = tid;   // 128 rows, 128 threads
        ull b1 = sred[(row * 2 + 0) * 3 + 0];
        ull b2 = sred[(row * 2 + 0) * 3 + 1];
        ull b3 = sred[(row * 2 + 0) * 3 + 2];
        merge3(b1, b2, b3,
               sred[(row * 2 + 1) * 3 + 0],
               sred[(row * 2 + 1) * 3 + 1],
               sred[(row * 2 + 1) * 3 + 2]);
        g_top1[(ull)(m0 + row) * NSPLITS + nblk] = b1;   // [token][split]
        g_top2[(ull)(m0 + row) * NSPLITS + nblk] = b2;
        g_top3[(ull)(m0 + row) * NSPLITS + nblk] = b3;
    }
}

// ---------------------------------------------------------------------------
// K2a: warp-per-token top-3 merge + near-tie exact fp32 fixup (3 candidates)
// ---------------------------------------------------------------------------
__global__ void k_assign(const float* __restrict__ z, const float* __restrict__ E,
                         float* __restrict__ out) {
    const int gtid = blockIdx.x * 256 + threadIdx.x;
    const int n    = gtid >> 5;          // token = warp
    const int lane = gtid & 31;
    if (n >= NTOK) return;

    const ull* t1p = g_top1 + (ull)n * NSPLITS;
    const ull* t2p = g_top2 + (ull)n * NSPLITS;
    const ull* t3p = g_top3 + (ull)n * NSPLITS;
    ull b1 = t1p[lane], b2 = t2p[lane], b3 = t3p[lane];
    merge3(b1, b2, b3, t1p[lane + 32], t2p[lane + 32], t3p[lane + 32]);
    #pragma unroll
    for (int sh = 16; sh >= 1; sh >>= 1) {
        ull o1 = __shfl_xor_sync(0xffffffffu, b1, sh);
        ull o2 = __shfl_xor_sync(0xffffffffu, b2, sh);
        ull o3 = __shfl_xor_sync(0xffffffffu, b3, sh);
        merge3(b1, b2, b3, o1, o2, o3);
    }

    int i1 = (KCODES - 1) - (int)(uint)(b1 & 0xffffffffu);
    int i2 = (KCODES - 1) - (int)(uint)(b2 & 0xffffffffu);
    int i3 = (KCODES - 1) - (int)(uint)(b3 & 0xffffffffu);
    uint m1 = ~(uint)(b1 >> 32), m2 = ~(uint)(b2 >> 32);
    float d1 = __uint_as_float((m1 & 0x80000000u) ? (m1 & 0x7fffffffu) : ~m1);
    float d2 = __uint_as_float((m2 & 0x80000000u) ? (m2 & 0x7fffffffu) : ~m2);

    int idx = i1;
    if (d2 - d1 < 1e-3f) {
        // exact fp32 re-score of all 3 candidates (reference-form distances)
        int b = n >> 10, hw = n & 1023;
        const float* zp  = z + b * DD * HW + hw;
        const float* ep1 = E + i1;
        const float* ep2 = E + i2;
        const float* ep3 = E + i3;
        float dot1 = 0.0f, dot2 = 0.0f, dot3 = 0.0f;
        #pragma unroll
        for (int t = 0; t < 8; t++) {
            int d = t * 32 + lane;
            float zv = zp[d * HW];
            dot1 = fmaf(zv, ep1[d * KCODES], dot1);
            dot2 = fmaf(zv, ep2[d * KCODES], dot2);
            dot3 = fmaf(zv, ep3[d * KCODES], dot3);
        }
        #pragma unroll
        for (int sh = 16; sh >= 1; sh >>= 1) {
            dot1 += __shfl_xor_sync(0xffffffffu, dot1, sh);
            dot2 += __shfl_xor_sync(0xffffffffu, dot2, sh);
            dot3 += __shfl_xor_sync(0xffffffffu, dot3, sh);
        }
        float sx2 = g_sx2[n];
        float e1x = (sx2 - 2.0f * dot1) + g_e2[i1];
        float e2x = (sx2 - 2.0f * dot2) + g_e2[i2];
        float e3x = (sx2 - 2.0f * dot3) + g_e2[i3];
        float be = e1x; int bi = i1;
        if (e2x < be || (e2x == be && i2 < bi)) { be = e2x; bi = i2; }
        if (e3x < be || (e3x == be && i3 < bi)) { be = e3x; bi = i3; }
        idx = bi;
    }
    if (lane == 0) {
        g_idx[n] = idx;
        out[OUT_IDX + n] = (float)idx;
        atomicAdd(&out[OUT_CS + idx], 1.0f);
    }
}

// ---------------------------------------------------------------------------
// K2b: gather quantized (NCHW), scatter dw, accumulate loss (vectorized x4)
// ---------------------------------------------------------------------------
__global__ void k_scatter(const float* __restrict__ z, const float* __restrict__ E,
                          float* __restrict__ out) {
    __shared__ float red[256];

    int tx  = threadIdx.x & 31;          // hw quad
    int ty  = threadIdx.x >> 5;          // d
    int hw4 = blockIdx.x * 128 + tx * 4;
    int d   = blockIdx.y * 8 + ty;
    int b   = blockIdx.z;

    int nb = b * HW + hw4;
    int4 idx4 = *(const int4*)&g_idx[nb];
    const float* Ed = E + (ull)d * KCODES;
    float q0 = Ed[idx4.x], q1 = Ed[idx4.y], q2 = Ed[idx4.z], q3 = Ed[idx4.w];

    int zi = (b * DD + d) * HW + hw4;
    float4 zv = *(const float4*)&z[zi];
    *(float4*)&out[OUT_Q + zi] = make_float4(q0, q1, q2, q3);

    float* dwd = out + OUT_DW + (ull)d * KCODES;
    atomicAdd(&dwd[idx4.x], zv.x);
    atomicAdd(&dwd[idx4.y], zv.y);
    atomicAdd(&dwd[idx4.z], zv.z);
    atomicAdd(&dwd[idx4.w], zv.w);

    float d0 = q0 - zv.x, d1 = q1 - zv.y, d2 = q2 - zv.z, d3 = q3 - zv.w;
    red[threadIdx.x] = d0 * d0 + d1 * d1 + d2 * d2 + d3 * d3;
    __syncthreads();
    #pragma unroll
    for (int s = 128; s > 0; s >>= 1) {
        if (threadIdx.x < s) red[threadIdx.x] += red[threadIdx.x + s];
        __syncthreads();
    }
    if (threadIdx.x == 0) atomicAdd(&g_loss, (double)red[0]);
}

// ---------------------------------------------------------------------------
// K3: loss + perplexity
// ---------------------------------------------------------------------------
__global__ void k_final(float* __restrict__ out) {
    __shared__ float red[256];
    int t = threadIdx.x;
    float s = 0.0f;
    for (int k = t; k < KCODES; k += 256) {
        float p = out[OUT_CS + k] * (1.0f / 8192.0f);
        s += p * logf(p + 1e-10f);
    }
    red[t] = s;
    __syncthreads();
    #pragma unroll
    for (int st = 128; st > 0; st >>= 1) {
        if (t < st) red[t] += red[t + st];
        __syncthreads();
    }
    if (t == 0) {
        out[OUT_PERP] = expf(-red[0]);
        out[OUT_LOSS] = (float)(0.25 * g_loss / 2097152.0);
    }
}

// ---------------------------------------------------------------------------
extern "C" void kernel_launch(void* const* d_in, const int* in_sizes, int n_in,
                              void* d_out, int out_size) {
    const float* z = (const float*)d_in[0];         // [8,256,32,32]
    const float* E = (const float*)d_in[1];         // [256,8192]
    float* out = (float*)d_out;

    cudaFuncSetAttribute(k_mma, cudaFuncAttributeMaxDynamicSharedMemorySize,
                         SMEM_DYN);

    k_prep   <<< 512, 256 >>>(z, E, out);
    k_mma    <<< dim3(NTOK / MTILE, NSPLITS), 128, SMEM_DYN >>>();
    k_assign <<< (NTOK * 32) / 256, 256 >>>(z, E, out);
    k_scatter<<< dim3(HW / 128, DD / 8, BATCH), 256 >>>(z, E, out);
    k_final  <<< 1, 256 >>>(out);
}